// round 8
// baseline (speedup 1.0000x reference)
#include <cuda_runtime.h>
#include <cuda_bf16.h>

#define NN 50000
#define NE 800000
#define INC 128
#define HID 96
#define OUTC 40
#define SCB 196   // scan blocks: 196*256 = 50176 >= NN

__device__ float g_dinv[NN];
__device__ float g_selfw[NN];
__device__ int   g_cnt[NN];
__device__ int   g_fill[NN];
__device__ int   g_rowptr[NN + 1];
__device__ int   g_bsum[256];
__device__ int   g_boff[256];
__device__ int   g_col[NE];
__device__ float g_ew[NE];
__device__ float g_t [NN * HID];
__device__ float g_t2[NN * HID];
__device__ float g_u [NN * HID];
__device__ float g_c [NN * OUTC];
__device__ float g_sum[3 * HID];
__device__ float g_sq [3 * HID];
__device__ float g_meanL[3][HID];
__device__ float g_sclL [3][HID];

// ---------------------------------------------------------------------------
// helpers
// ---------------------------------------------------------------------------
typedef unsigned long long ull;

__device__ __forceinline__ void ffma2(ull& acc, ull a2, ull b2) {
    asm("fma.rn.f32x2 %0, %1, %2, %3;" : "=l"(acc) : "l"(a2), "l"(b2), "l"(acc));
}
__device__ __forceinline__ float2 unpack2(ull v) {
    float2 r;
    asm("mov.b64 {%0, %1}, %2;" : "=f"(r.x), "=f"(r.y) : "l"(v));
    return r;
}
__device__ __forceinline__ unsigned su32(const void* p) {
    return (unsigned)__cvta_generic_to_shared(p);
}
__device__ __forceinline__ ull lds64(unsigned a) {
    ull v;
    asm volatile("ld.shared.b64 %0, [%1];" : "=l"(v) : "r"(a));
    return v;
}

// ---------------------------------------------------------------------------
// Prep
// ---------------------------------------------------------------------------
__global__ void zero_prep_kernel() {
    int i = blockIdx.x * blockDim.x + threadIdx.x;
    if (i < NN) { g_cnt[i] = 0; g_fill[i] = 0; }
    if (i < 3 * HID) { g_sum[i] = 0.f; g_sq[i] = 0.f; }
}

__global__ void cnt_kernel(const int* __restrict__ ei) {
    int e = blockIdx.x * blockDim.x + threadIdx.x;
    if (e >= NE) return;
    int s = ei[e];
    int d = ei[NE + e];
    if (s != d) atomicAdd(&g_cnt[d], 1);
}

__global__ void scan1_kernel() {
    __shared__ int sh[256];
    int i = blockIdx.x * 256 + threadIdx.x;
    sh[threadIdx.x] = (i < NN) ? g_cnt[i] : 0;
    __syncthreads();
    for (int o = 128; o > 0; o >>= 1) {
        if (threadIdx.x < o) sh[threadIdx.x] += sh[threadIdx.x + o];
        __syncthreads();
    }
    if (threadIdx.x == 0) g_bsum[blockIdx.x] = sh[0];
}

__global__ void scan2_kernel() {
    __shared__ int sh[256];
    int t = threadIdx.x;
    int v = (t < SCB) ? g_bsum[t] : 0;
    sh[t] = v;
    __syncthreads();
    for (int o = 1; o < 256; o <<= 1) {
        int add = (t >= o) ? sh[t - o] : 0;
        __syncthreads();
        sh[t] += add;
        __syncthreads();
    }
    if (t < SCB) g_boff[t] = sh[t] - v;
    if (t == 255) g_rowptr[NN] = sh[255];
}

__global__ void scan3_kernel() {
    __shared__ int sh[256];
    int t = threadIdx.x;
    int i = blockIdx.x * 256 + t;
    int v = (i < NN) ? g_cnt[i] : 0;
    sh[t] = v;
    __syncthreads();
    for (int o = 1; o < 256; o <<= 1) {
        int add = (t >= o) ? sh[t - o] : 0;
        __syncthreads();
        sh[t] += add;
        __syncthreads();
    }
    if (i < NN) {
        g_rowptr[i] = g_boff[blockIdx.x] + sh[t] - v;
        float d = (float)v + 1.f;
        g_dinv[i]  = rsqrtf(d);
        g_selfw[i] = 1.f / d;
    }
}

__global__ void fill_kernel(const int* __restrict__ ei) {
    int e = blockIdx.x * blockDim.x + threadIdx.x;
    if (e >= NE) return;
    int s = ei[e];
    int d = ei[NE + e];
    if (s == d) return;
    int pos = g_rowptr[d] + atomicAdd(&g_fill[d], 1);
    g_col[pos] = s;
    g_ew[pos] = g_dinv[s] * g_dinv[d];
}

// ---------------------------------------------------------------------------
// SGEMM (R6 config): W SMEM-resident (K-major, stride NOUT+2), A tile stored
// DUPLICATED (float2(v,v)) + double-buffered. Inner loop pure LDS.64 + FFMA2.
// OCC = min-blocks-per-SM hint (occupancy target).
// Requires: TX*TY=256, TM*TY=128, TX*2*TNP=NOUT, K%16==0.
// ---------------------------------------------------------------------------
template <int K, int NOUT, int TM, int TNP, int TX, int TY, int NORM, int STATS, int OCC>
__global__ void __launch_bounds__(256, OCC)
gemm_kernel(const float* __restrict__ A,
            const float* __restrict__ Wg,
            float* __restrict__ Out,
            const float* __restrict__ blendSrc,
            const float* __restrict__ mean,
            const float* __restrict__ scl,
            float beta,
            float* __restrict__ sums,
            float* __restrict__ sq) {
    constexpr int BM = TM * TY;         // 128
    constexpr int NT = TX * TY;         // 256
    constexpr int WSTR = NOUT + 2;
    constexpr int NC = K / 16;
    constexpr int CN = 2 * TNP;

    extern __shared__ char smem[];
    float*  ws   = (float*)smem;                                  // K*WSTR
    float2* xs   = (float2*)(smem + K * WSTR * 4);                // 2*16*BM
    float*  ssum = (float*)(smem + K * WSTR * 4 + 2 * 16 * BM * 8);
    float*  ssq  = ssum + NOUT;

    int tid = threadIdx.x;
    int tx = tid % TX;
    int ty = tid / TX;
    int rowbase = blockIdx.x * BM;

    if (STATS) {
        for (int i = tid; i < NOUT; i += NT) { ssum[i] = 0.f; ssq[i] = 0.f; }
    }

    // ---- load W transposed into SMEM (once) ----
    constexpr int K4 = K / 4;
    for (int i = tid; i < NOUT * K4; i += NT) {
        int n = i / K4, q = i % K4;
        float4 w = __ldg((const float4*)&Wg[(size_t)n * K + q * 4]);
        ws[(q * 4 + 0) * WSTR + n] = w.x;
        ws[(q * 4 + 1) * WSTR + n] = w.y;
        ws[(q * 4 + 2) * WSTR + n] = w.z;
        ws[(q * 4 + 3) * WSTR + n] = w.w;
    }

    auto ldA = [&](int ch, int i) -> float4 {
        int r = i >> 2, c4 = (i & 3) * 4;
        int row = rowbase + r;
        int k = ch * 16 + c4;
        float4 v = (row < NN) ? __ldg((const float4*)&A[(size_t)row * K + k])
                              : make_float4(0.f, 0.f, 0.f, 0.f);
        if (NORM) {
            float4 m = __ldg((const float4*)&mean[k]);
            float4 s = __ldg((const float4*)&scl[k]);
            v.x = fmaxf((v.x - m.x) * s.x, 0.f);
            v.y = fmaxf((v.y - m.y) * s.y, 0.f);
            v.z = fmaxf((v.z - m.z) * s.z, 0.f);
            v.w = fmaxf((v.w - m.w) * s.w, 0.f);
        }
        return v;
    };
    auto stA = [&](int buf, int i, float4 v) {
        int r = i >> 2, c4 = (i & 3) * 4;
        float2* base = &xs[(size_t)(buf * 16) * BM + r];
        base[(c4 + 0) * BM] = make_float2(v.x, v.x);
        base[(c4 + 1) * BM] = make_float2(v.y, v.y);
        base[(c4 + 2) * BM] = make_float2(v.z, v.z);
        base[(c4 + 3) * BM] = make_float2(v.w, v.w);
    };

    stA(0, tid, ldA(0, tid));
    stA(0, tid + 256, ldA(0, tid + 256));
    __syncthreads();

    ull acc2[TM][TNP];
#pragma unroll
    for (int r = 0; r < TM; r++)
#pragma unroll
        for (int c = 0; c < TNP; c++) acc2[r][c] = 0ull;

    unsigned athr = su32(xs) + (unsigned)(ty * TM) * 8u;
    unsigned bthr = su32(ws) + (unsigned)(tx * CN) * 4u;

#pragma unroll 2
    for (int ch = 0; ch < NC; ch++) {
        bool pre = (ch + 1 < NC);
        float4 p0, p1;
        if (pre) { p0 = ldA(ch + 1, tid); p1 = ldA(ch + 1, tid + 256); }

        unsigned abase = athr + (unsigned)((ch & 1) * 16 * BM) * 8u;
        unsigned bbase = bthr + (unsigned)(ch * 16 * WSTR) * 4u;
#pragma unroll
        for (int kk = 0; kk < 16; kk++) {
            ull a2[TM], b2[TNP];
#pragma unroll
            for (int r = 0; r < TM; r++)
                a2[r] = lds64(abase + (unsigned)(kk * BM + r) * 8u);
#pragma unroll
            for (int c = 0; c < TNP; c++)
                b2[c] = lds64(bbase + (unsigned)(kk * WSTR) * 4u + (unsigned)c * 8u);
#pragma unroll
            for (int r = 0; r < TM; r++)
#pragma unroll
                for (int c = 0; c < TNP; c++) ffma2(acc2[r][c], a2[r], b2[c]);
        }

        if (pre) {
            int buf = (ch + 1) & 1;
            stA(buf, tid, p0);
            stA(buf, tid + 256, p1);
        }
        __syncthreads();
    }

    // ---- epilogue ----
    float colsum[CN], colsq[CN];
    if (STATS) {
#pragma unroll
        for (int c = 0; c < CN; c++) { colsum[c] = 0.f; colsq[c] = 0.f; }
    }

#pragma unroll
    for (int r = 0; r < TM; r++) {
        int row = rowbase + ty * TM + r;
        if (row >= NN) continue;
#pragma unroll
        for (int c = 0; c < TNP; c++) {
            int col = tx * CN + 2 * c;
            float2 v = unpack2(acc2[r][c]);
            if (beta != 1.f) {
                float2 b = *(const float2*)&blendSrc[(size_t)row * NOUT + col];
                if (NORM) {
                    b.x = fmaxf((b.x - mean[col + 0]) * scl[col + 0], 0.f);
                    b.y = fmaxf((b.y - mean[col + 1]) * scl[col + 1], 0.f);
                }
                v.x = beta * v.x + (1.f - beta) * b.x;
                v.y = beta * v.y + (1.f - beta) * b.y;
            }
            *(float2*)&Out[(size_t)row * NOUT + col] = v;
            if (STATS) {
                colsum[2 * c] += v.x;     colsq[2 * c] += v.x * v.x;
                colsum[2 * c + 1] += v.y; colsq[2 * c + 1] += v.y * v.y;
            }
        }
    }

    if (STATS) {
#pragma unroll
        for (int c = 0; c < CN; c++) {
            atomicAdd(&ssum[tx * CN + c], colsum[c]);
            atomicAdd(&ssq[tx * CN + c], colsq[c]);
        }
        __syncthreads();
        for (int i = tid; i < NOUT; i += NT) {
            atomicAdd(&sums[i], ssum[i]);
            atomicAdd(&sq[i], ssq[i]);
        }
    }
}

// ---------------------------------------------------------------------------
// BN finalize
// ---------------------------------------------------------------------------
__global__ void bn_final_kernel(const float* __restrict__ sums,
                                const float* __restrict__ sq,
                                float* __restrict__ mean,
                                float* __restrict__ scl) {
    int c = threadIdx.x;
    if (c < HID) {
        const float invN = 1.f / (float)NN;
        float m = sums[c] * invN;
        float v = sq[c] * invN - m * m;
        mean[c] = m;
        scl[c] = rsqrtf(v + 1e-5f);
    }
}

// ---------------------------------------------------------------------------
// CSR gather SpMM, warp per node, float4 lanes, edge loop unrolled x4.
// ---------------------------------------------------------------------------
template <int F, int MODE>
__global__ void gather_kernel(const float* __restrict__ X, float* __restrict__ Y,
                              const float* __restrict__ h0raw,
                              const float* __restrict__ mean0,
                              const float* __restrict__ scl0,
                              float* __restrict__ sums,
                              float* __restrict__ sq) {
    constexpr int NV = F / 4;
    __shared__ float ssum[HID];
    __shared__ float ssq[HID];
    int tid = threadIdx.x;
    if (MODE == 1) {
        if (tid < F) { ssum[tid] = 0.f; ssq[tid] = 0.f; }
        __syncthreads();
    }
    int node = blockIdx.x * (blockDim.x >> 5) + (tid >> 5);
    int lane = tid & 31;
    bool act = lane < NV;
    const float4* Xv = (const float4*)X;

    float4 sum = make_float4(0.f, 0.f, 0.f, 0.f);
    int p   = g_rowptr[node];
    int end = g_rowptr[node + 1];

    for (; p + 4 <= end; p += 4) {
        int   c0 = __ldg(&g_col[p]),     c1 = __ldg(&g_col[p + 1]);
        int   c2 = __ldg(&g_col[p + 2]), c3 = __ldg(&g_col[p + 3]);
        float w0 = __ldg(&g_ew[p]),      w1 = __ldg(&g_ew[p + 1]);
        float w2 = __ldg(&g_ew[p + 2]),  w3 = __ldg(&g_ew[p + 3]);
        if (act) {
            float4 v0 = __ldg(&Xv[(size_t)c0 * NV + lane]);
            float4 v1 = __ldg(&Xv[(size_t)c1 * NV + lane]);
            float4 v2 = __ldg(&Xv[(size_t)c2 * NV + lane]);
            float4 v3 = __ldg(&Xv[(size_t)c3 * NV + lane]);
            sum.x += w0 * v0.x + w1 * v1.x + w2 * v2.x + w3 * v3.x;
            sum.y += w0 * v0.y + w1 * v1.y + w2 * v2.y + w3 * v3.y;
            sum.z += w0 * v0.z + w1 * v1.z + w2 * v2.z + w3 * v3.z;
            sum.w += w0 * v0.w + w1 * v1.w + w2 * v2.w + w3 * v3.w;
        }
    }
    for (; p < end; p++) {
        int c = __ldg(&g_col[p]);
        float w = __ldg(&g_ew[p]);
        if (act) {
            float4 v = __ldg(&Xv[(size_t)c * NV + lane]);
            sum.x += w * v.x; sum.y += w * v.y;
            sum.z += w * v.z; sum.w += w * v.w;
        }
    }

    if (act) {
        float sw = g_selfw[node];
        float4 xv = __ldg(&Xv[(size_t)node * NV + lane]);
        float4 v;
        v.x = sum.x + sw * xv.x;
        v.y = sum.y + sw * xv.y;
        v.z = sum.z + sw * xv.z;
        v.w = sum.w + sw * xv.w;
        if (MODE == 1) {
            float4 m  = __ldg(&((const float4*)mean0)[lane]);
            float4 s  = __ldg(&((const float4*)scl0)[lane]);
            float4 hr = __ldg(&((const float4*)h0raw)[(size_t)node * NV + lane]);
            v.x = 0.9f * v.x + 0.1f * fmaxf((hr.x - m.x) * s.x, 0.f);
            v.y = 0.9f * v.y + 0.1f * fmaxf((hr.y - m.y) * s.y, 0.f);
            v.z = 0.9f * v.z + 0.1f * fmaxf((hr.z - m.z) * s.z, 0.f);
            v.w = 0.9f * v.w + 0.1f * fmaxf((hr.w - m.w) * s.w, 0.f);
        }
        ((float4*)Y)[(size_t)node * NV + lane] = v;
        if (MODE == 1) {
            int col = lane * 4;
            atomicAdd(&ssum[col + 0], v.x);
            atomicAdd(&ssum[col + 1], v.y);
            atomicAdd(&ssum[col + 2], v.z);
            atomicAdd(&ssum[col + 3], v.w);
            atomicAdd(&ssq[col + 0], v.x * v.x);
            atomicAdd(&ssq[col + 1], v.y * v.y);
            atomicAdd(&ssq[col + 2], v.z * v.z);
            atomicAdd(&ssq[col + 3], v.w * v.w);
        }
    }

    if (MODE == 1) {
        __syncthreads();
        if (tid < F) {
            atomicAdd(&sums[tid], ssum[tid]);
            atomicAdd(&sq[tid], ssq[tid]);
        }
    }
}

// ---------------------------------------------------------------------------
extern "C" void kernel_launch(void* const* d_in, const int* in_sizes, int n_in,
                              void* d_out, int out_size) {
    const float* x  = (const float*)d_in[0];
    const int*   ei = (const int*)d_in[1];
    const float* W0 = (const float*)d_in[2];
    const float* W1 = (const float*)d_in[3];
    const float* W2 = (const float*)d_in[4];
    const float* W3 = (const float*)d_in[5];
    float* out = (float*)d_out;

    float *pt, *pt2, *pu, *pc, *psum, *psq, *pmean, *pscl;
    cudaGetSymbolAddress((void**)&pt, g_t);
    cudaGetSymbolAddress((void**)&pt2, g_t2);
    cudaGetSymbolAddress((void**)&pu, g_u);
    cudaGetSymbolAddress((void**)&pc, g_c);
    cudaGetSymbolAddress((void**)&psum, g_sum);
    cudaGetSymbolAddress((void**)&psq, g_sq);
    cudaGetSymbolAddress((void**)&pmean, g_meanL);
    cudaGetSymbolAddress((void**)&pscl, g_sclL);

    const int gbE = (NE + 255) / 256;
    const int gbN = (NN + 255) / 256;
    const int gbG = (NN + 127) / 128;
    const int gbW = NN / 16;

    float* m0 = pmean + 0 * HID; float* s0 = pscl + 0 * HID;
    float* m1 = pmean + 1 * HID; float* s1 = pscl + 1 * HID;
    float* m2 = pmean + 2 * HID; float* s2 = pscl + 2 * HID;

    // dynamic smem: ws + dup A double buffer + stats
    const int xsBytes = 2 * 16 * 128 * 8;  // 32768
    const int sm0 = 128 * 98 * 4 + xsBytes + 96 * 8 + 64;   // ~83.9 KB -> 2 CTAs
    const int sm1 = 96 * 98 * 4 + xsBytes + 96 * 8 + 64;    // ~71.2 KB -> 3 CTAs
    const int sm3 = 96 * 42 * 4 + xsBytes + 40 * 8 + 64;    // ~49.3 KB -> 3 CTAs

    auto k0  = gemm_kernel<INC, HID, 8, 3, 16, 16, 0, 1, 2>;
    auto k12 = gemm_kernel<HID, HID, 8, 3, 16, 16, 1, 0, 3>;
    auto k3  = gemm_kernel<HID, OUTC, 2, 5, 4, 64, 1, 0, 3>;
    cudaFuncSetAttribute(k0, cudaFuncAttributeMaxDynamicSharedMemorySize, sm0);
    cudaFuncSetAttribute(k12, cudaFuncAttributeMaxDynamicSharedMemorySize, sm1);
    cudaFuncSetAttribute(k3, cudaFuncAttributeMaxDynamicSharedMemorySize, sm3);

    // ---- prep + layer-0 GEMM (slot 4 for the ncu capture window) ----
    zero_prep_kernel<<<gbN, 256>>>();
    cnt_kernel<<<gbE, 256>>>(ei);
    scan1_kernel<<<SCB, 256>>>();
    k0<<<gbG, 256, sm0>>>(x, W0, pt, nullptr, nullptr, nullptr, 1.f,
                          psum + 0 * HID, psq + 0 * HID);
    scan2_kernel<<<1, 256>>>();
    scan3_kernel<<<SCB, 256>>>();
    fill_kernel<<<gbE, 256>>>(ei);
    bn_final_kernel<<<1, HID>>>(psum + 0 * HID, psq + 0 * HID, m0, s0);

    // ---- layer 1 (beta = 0.5) ----
    k12<<<gbG, 256, sm1>>>(pt, W1, pt2, pt, m0, s0, 0.5f, nullptr, nullptr);
    gather_kernel<HID, 1><<<gbW, 512>>>(pt2, pu, pt, m0, s0, psum + 1 * HID, psq + 1 * HID);
    bn_final_kernel<<<1, HID>>>(psum + 1 * HID, psq + 1 * HID, m1, s1);

    // ---- layer 2 (beta = 0.25) ----
    k12<<<gbG, 256, sm1>>>(pu, W2, pt2, pu, m1, s1, 0.25f, nullptr, nullptr);
    gather_kernel<HID, 1><<<gbW, 512>>>(pt2, pu, pt, m0, s0, psum + 2 * HID, psq + 2 * HID);
    bn_final_kernel<<<1, HID>>>(psum + 2 * HID, psq + 2 * HID, m2, s2);

    // ---- final: c = bn2relu(u) @ W3^T ; out = spmm(c) ----
    k3<<<gbG, 256, sm3>>>(pu, W3, pc, nullptr, m2, s2, 1.f, nullptr, nullptr);
    gather_kernel<OUTC, 0><<<gbW, 512>>>(pc, out, nullptr, nullptr, nullptr, nullptr, nullptr);
}

// round 9
// speedup vs baseline: 1.3761x; 1.3761x over previous
#include <cuda_runtime.h>
#include <cuda_bf16.h>

#define NN 50000
#define NE 800000
#define INC 128
#define HID 96
#define OUTC 40
#define SCB 196   // scan blocks: 196*256 = 50176 >= NN

__device__ float g_dinv[NN];
__device__ float g_selfw[NN];
__device__ int   g_cnt[NN];
__device__ int   g_fill[NN];
__device__ int   g_rowptr[NN + 1];
__device__ int   g_bsum[256];
__device__ int   g_boff[256];
__device__ int   g_col[NE];
__device__ float g_ew[NE];
__device__ float g_t [NN * HID];
__device__ float g_t2[NN * HID];
__device__ float g_u [NN * HID];
__device__ float g_c [NN * OUTC];
__device__ float g_sum[3 * HID];
__device__ float g_sq [3 * HID];
__device__ float g_meanL[3][HID];
__device__ float g_sclL [3][HID];

// ---------------------------------------------------------------------------
// helpers
// ---------------------------------------------------------------------------
typedef unsigned long long ull;

__device__ __forceinline__ void ffma2(ull& acc, ull a2, ull b2) {
    asm("fma.rn.f32x2 %0, %1, %2, %3;" : "=l"(acc) : "l"(a2), "l"(b2), "l"(acc));
}
__device__ __forceinline__ float2 unpack2(ull v) {
    float2 r;
    asm("mov.b64 {%0, %1}, %2;" : "=f"(r.x), "=f"(r.y) : "l"(v));
    return r;
}
__device__ __forceinline__ unsigned su32(const void* p) {
    return (unsigned)__cvta_generic_to_shared(p);
}
__device__ __forceinline__ ull lds64(unsigned a) {
    ull v;
    asm volatile("ld.shared.b64 %0, [%1];" : "=l"(v) : "r"(a));
    return v;
}

// ---------------------------------------------------------------------------
// Prep
// ---------------------------------------------------------------------------
__global__ void zero_prep_kernel() {
    int i = blockIdx.x * blockDim.x + threadIdx.x;
    if (i < NN) { g_cnt[i] = 0; g_fill[i] = 0; }
    if (i < 3 * HID) { g_sum[i] = 0.f; g_sq[i] = 0.f; }
}

__global__ void cnt_kernel(const int* __restrict__ ei) {
    int e = blockIdx.x * blockDim.x + threadIdx.x;
    if (e >= NE) return;
    int s = ei[e];
    int d = ei[NE + e];
    if (s != d) atomicAdd(&g_cnt[d], 1);
}

__global__ void scan1_kernel() {
    __shared__ int sh[256];
    int i = blockIdx.x * 256 + threadIdx.x;
    sh[threadIdx.x] = (i < NN) ? g_cnt[i] : 0;
    __syncthreads();
    for (int o = 128; o > 0; o >>= 1) {
        if (threadIdx.x < o) sh[threadIdx.x] += sh[threadIdx.x + o];
        __syncthreads();
    }
    if (threadIdx.x == 0) g_bsum[blockIdx.x] = sh[0];
}

__global__ void scan2_kernel() {
    __shared__ int sh[256];
    int t = threadIdx.x;
    int v = (t < SCB) ? g_bsum[t] : 0;
    sh[t] = v;
    __syncthreads();
    for (int o = 1; o < 256; o <<= 1) {
        int add = (t >= o) ? sh[t - o] : 0;
        __syncthreads();
        sh[t] += add;
        __syncthreads();
    }
    if (t < SCB) g_boff[t] = sh[t] - v;
    if (t == 255) g_rowptr[NN] = sh[255];
}

__global__ void scan3_kernel() {
    __shared__ int sh[256];
    int t = threadIdx.x;
    int i = blockIdx.x * 256 + t;
    int v = (i < NN) ? g_cnt[i] : 0;
    sh[t] = v;
    __syncthreads();
    for (int o = 1; o < 256; o <<= 1) {
        int add = (t >= o) ? sh[t - o] : 0;
        __syncthreads();
        sh[t] += add;
        __syncthreads();
    }
    if (i < NN) {
        g_rowptr[i] = g_boff[blockIdx.x] + sh[t] - v;
        float d = (float)v + 1.f;
        g_dinv[i]  = rsqrtf(d);
        g_selfw[i] = 1.f / d;
    }
}

__global__ void fill_kernel(const int* __restrict__ ei) {
    int e = blockIdx.x * blockDim.x + threadIdx.x;
    if (e >= NE) return;
    int s = ei[e];
    int d = ei[NE + e];
    if (s == d) return;
    int pos = g_rowptr[d] + atomicAdd(&g_fill[d], 1);
    g_col[pos] = s;
    g_ew[pos] = g_dinv[s] * g_dinv[d];
}

// ---------------------------------------------------------------------------
// SGEMM (R6 structure, BM generalized): W SMEM-resident (K-major, stride
// NOUT+2), A tile DUPLICATED (float2(v,v)) + double-buffered. Inner loop pure
// LDS.64 + FFMA2. Requires: TX*TY=256, TX*2*TNP=NOUT, K%16==0.
// ---------------------------------------------------------------------------
template <int K, int NOUT, int TM, int TNP, int TX, int TY, int NORM, int STATS>
__global__ void __launch_bounds__(256)
gemm_kernel(const float* __restrict__ A,
            const float* __restrict__ Wg,
            float* __restrict__ Out,
            const float* __restrict__ blendSrc,
            const float* __restrict__ mean,
            const float* __restrict__ scl,
            float beta,
            float* __restrict__ sums,
            float* __restrict__ sq) {
    constexpr int BM = TM * TY;
    constexpr int NT = TX * TY;         // 256
    constexpr int WSTR = NOUT + 2;
    constexpr int NC = K / 16;
    constexpr int CN = 2 * TNP;
    constexpr int NLD = (BM * 4 + NT - 1) / NT;   // staging iters per chunk

    extern __shared__ char smem[];
    float*  ws   = (float*)smem;                                  // K*WSTR
    float2* xs   = (float2*)(smem + K * WSTR * 4);                // 2*16*BM
    float*  ssum = (float*)(smem + K * WSTR * 4 + 2 * 16 * BM * 8);
    float*  ssq  = ssum + NOUT;

    int tid = threadIdx.x;
    int tx = tid % TX;
    int ty = tid / TX;
    int rowbase = blockIdx.x * BM;

    if (STATS) {
        for (int i = tid; i < NOUT; i += NT) { ssum[i] = 0.f; ssq[i] = 0.f; }
    }

    // ---- load W transposed into SMEM (once) ----
    constexpr int K4 = K / 4;
    for (int i = tid; i < NOUT * K4; i += NT) {
        int n = i / K4, q = i % K4;
        float4 w = __ldg((const float4*)&Wg[(size_t)n * K + q * 4]);
        ws[(q * 4 + 0) * WSTR + n] = w.x;
        ws[(q * 4 + 1) * WSTR + n] = w.y;
        ws[(q * 4 + 2) * WSTR + n] = w.z;
        ws[(q * 4 + 3) * WSTR + n] = w.w;
    }

    auto ldA = [&](int ch, int i) -> float4 {
        int r = i >> 2, c4 = (i & 3) * 4;
        int row = rowbase + r;
        int k = ch * 16 + c4;
        float4 v = (row < NN) ? __ldg((const float4*)&A[(size_t)row * K + k])
                              : make_float4(0.f, 0.f, 0.f, 0.f);
        if (NORM) {
            float4 m = __ldg((const float4*)&mean[k]);
            float4 s = __ldg((const float4*)&scl[k]);
            v.x = fmaxf((v.x - m.x) * s.x, 0.f);
            v.y = fmaxf((v.y - m.y) * s.y, 0.f);
            v.z = fmaxf((v.z - m.z) * s.z, 0.f);
            v.w = fmaxf((v.w - m.w) * s.w, 0.f);
        }
        return v;
    };
    auto stA = [&](int buf, int i, float4 v) {
        int r = i >> 2, c4 = (i & 3) * 4;
        float2* base = &xs[(size_t)(buf * 16) * BM + r];
        base[(c4 + 0) * BM] = make_float2(v.x, v.x);
        base[(c4 + 1) * BM] = make_float2(v.y, v.y);
        base[(c4 + 2) * BM] = make_float2(v.z, v.z);
        base[(c4 + 3) * BM] = make_float2(v.w, v.w);
    };

#pragma unroll
    for (int j = 0; j < NLD; j++) {
        int i = tid + j * NT;
        if (i < BM * 4) stA(0, i, ldA(0, i));
    }
    __syncthreads();

    ull acc2[TM][TNP];
#pragma unroll
    for (int r = 0; r < TM; r++)
#pragma unroll
        for (int c = 0; c < TNP; c++) acc2[r][c] = 0ull;

    unsigned athr = su32(xs) + (unsigned)(ty * TM) * 8u;
    unsigned bthr = su32(ws) + (unsigned)(tx * CN) * 4u;

#pragma unroll 2
    for (int ch = 0; ch < NC; ch++) {
        bool pre = (ch + 1 < NC);
        float4 p[NLD];
        if (pre) {
#pragma unroll
            for (int j = 0; j < NLD; j++) {
                int i = tid + j * NT;
                if (i < BM * 4) p[j] = ldA(ch + 1, i);
            }
        }

        unsigned abase = athr + (unsigned)((ch & 1) * 16 * BM) * 8u;
        unsigned bbase = bthr + (unsigned)(ch * 16 * WSTR) * 4u;
#pragma unroll
        for (int kk = 0; kk < 16; kk++) {
            ull a2[TM], b2[TNP];
#pragma unroll
            for (int r = 0; r < TM; r++)
                a2[r] = lds64(abase + (unsigned)(kk * BM + r) * 8u);
#pragma unroll
            for (int c = 0; c < TNP; c++)
                b2[c] = lds64(bbase + (unsigned)(kk * WSTR) * 4u + (unsigned)c * 8u);
#pragma unroll
            for (int r = 0; r < TM; r++)
#pragma unroll
                for (int c = 0; c < TNP; c++) ffma2(acc2[r][c], a2[r], b2[c]);
        }

        if (pre) {
            int buf = (ch + 1) & 1;
#pragma unroll
            for (int j = 0; j < NLD; j++) {
                int i = tid + j * NT;
                if (i < BM * 4) stA(buf, i, p[j]);
            }
        }
        __syncthreads();
    }

    // ---- epilogue ----
    float colsum[CN], colsq[CN];
    if (STATS) {
#pragma unroll
        for (int c = 0; c < CN; c++) { colsum[c] = 0.f; colsq[c] = 0.f; }
    }

#pragma unroll
    for (int r = 0; r < TM; r++) {
        int row = rowbase + ty * TM + r;
        if (row >= NN) continue;
#pragma unroll
        for (int c = 0; c < TNP; c++) {
            int col = tx * CN + 2 * c;
            float2 v = unpack2(acc2[r][c]);
            if (beta != 1.f) {
                float2 b = *(const float2*)&blendSrc[(size_t)row * NOUT + col];
                if (NORM) {
                    b.x = fmaxf((b.x - mean[col + 0]) * scl[col + 0], 0.f);
                    b.y = fmaxf((b.y - mean[col + 1]) * scl[col + 1], 0.f);
                }
                v.x = beta * v.x + (1.f - beta) * b.x;
                v.y = beta * v.y + (1.f - beta) * b.y;
            }
            *(float2*)&Out[(size_t)row * NOUT + col] = v;
            if (STATS) {
                colsum[2 * c] += v.x;     colsq[2 * c] += v.x * v.x;
                colsum[2 * c + 1] += v.y; colsq[2 * c + 1] += v.y * v.y;
            }
        }
    }

    if (STATS) {
#pragma unroll
        for (int c = 0; c < CN; c++) {
            atomicAdd(&ssum[tx * CN + c], colsum[c]);
            atomicAdd(&ssq[tx * CN + c], colsq[c]);
        }
        __syncthreads();
        for (int i = tid; i < NOUT; i += NT) {
            atomicAdd(&sums[i], ssum[i]);
            atomicAdd(&sq[i], ssq[i]);
        }
    }
}

// ---------------------------------------------------------------------------
// BN finalize
// ---------------------------------------------------------------------------
__global__ void bn_final_kernel(const float* __restrict__ sums,
                                const float* __restrict__ sq,
                                float* __restrict__ mean,
                                float* __restrict__ scl) {
    int c = threadIdx.x;
    if (c < HID) {
        const float invN = 1.f / (float)NN;
        float m = sums[c] * invN;
        float v = sq[c] * invN - m * m;
        mean[c] = m;
        scl[c] = rsqrtf(v + 1e-5f);
    }
}

// ---------------------------------------------------------------------------
// CSR gather SpMM, warp per node, float4 lanes, edge loop unrolled x4.
// ---------------------------------------------------------------------------
template <int F, int MODE>
__global__ void gather_kernel(const float* __restrict__ X, float* __restrict__ Y,
                              const float* __restrict__ h0raw,
                              const float* __restrict__ mean0,
                              const float* __restrict__ scl0,
                              float* __restrict__ sums,
                              float* __restrict__ sq) {
    constexpr int NV = F / 4;
    __shared__ float ssum[HID];
    __shared__ float ssq[HID];
    int tid = threadIdx.x;
    if (MODE == 1) {
        if (tid < F) { ssum[tid] = 0.f; ssq[tid] = 0.f; }
        __syncthreads();
    }
    int node = blockIdx.x * (blockDim.x >> 5) + (tid >> 5);
    int lane = tid & 31;
    bool act = lane < NV;
    const float4* Xv = (const float4*)X;

    float4 sum = make_float4(0.f, 0.f, 0.f, 0.f);
    int p   = g_rowptr[node];
    int end = g_rowptr[node + 1];

    for (; p + 4 <= end; p += 4) {
        int   c0 = __ldg(&g_col[p]),     c1 = __ldg(&g_col[p + 1]);
        int   c2 = __ldg(&g_col[p + 2]), c3 = __ldg(&g_col[p + 3]);
        float w0 = __ldg(&g_ew[p]),      w1 = __ldg(&g_ew[p + 1]);
        float w2 = __ldg(&g_ew[p + 2]),  w3 = __ldg(&g_ew[p + 3]);
        if (act) {
            float4 v0 = __ldg(&Xv[(size_t)c0 * NV + lane]);
            float4 v1 = __ldg(&Xv[(size_t)c1 * NV + lane]);
            float4 v2 = __ldg(&Xv[(size_t)c2 * NV + lane]);
            float4 v3 = __ldg(&Xv[(size_t)c3 * NV + lane]);
            sum.x += w0 * v0.x + w1 * v1.x + w2 * v2.x + w3 * v3.x;
            sum.y += w0 * v0.y + w1 * v1.y + w2 * v2.y + w3 * v3.y;
            sum.z += w0 * v0.z + w1 * v1.z + w2 * v2.z + w3 * v3.z;
            sum.w += w0 * v0.w + w1 * v1.w + w2 * v2.w + w3 * v3.w;
        }
    }
    for (; p < end; p++) {
        int c = __ldg(&g_col[p]);
        float w = __ldg(&g_ew[p]);
        if (act) {
            float4 v = __ldg(&Xv[(size_t)c * NV + lane]);
            sum.x += w * v.x; sum.y += w * v.y;
            sum.z += w * v.z; sum.w += w * v.w;
        }
    }

    if (act) {
        float sw = g_selfw[node];
        float4 xv = __ldg(&Xv[(size_t)node * NV + lane]);
        float4 v;
        v.x = sum.x + sw * xv.x;
        v.y = sum.y + sw * xv.y;
        v.z = sum.z + sw * xv.z;
        v.w = sum.w + sw * xv.w;
        if (MODE == 1) {
            float4 m  = __ldg(&((const float4*)mean0)[lane]);
            float4 s  = __ldg(&((const float4*)scl0)[lane]);
            float4 hr = __ldg(&((const float4*)h0raw)[(size_t)node * NV + lane]);
            v.x = 0.9f * v.x + 0.1f * fmaxf((hr.x - m.x) * s.x, 0.f);
            v.y = 0.9f * v.y + 0.1f * fmaxf((hr.y - m.y) * s.y, 0.f);
            v.z = 0.9f * v.z + 0.1f * fmaxf((hr.z - m.z) * s.z, 0.f);
            v.w = 0.9f * v.w + 0.1f * fmaxf((hr.w - m.w) * s.w, 0.f);
        }
        ((float4*)Y)[(size_t)node * NV + lane] = v;
        if (MODE == 1) {
            int col = lane * 4;
            atomicAdd(&ssum[col + 0], v.x);
            atomicAdd(&ssum[col + 1], v.y);
            atomicAdd(&ssum[col + 2], v.z);
            atomicAdd(&ssum[col + 3], v.w);
            atomicAdd(&ssq[col + 0], v.x * v.x);
            atomicAdd(&ssq[col + 1], v.y * v.y);
            atomicAdd(&ssq[col + 2], v.z * v.z);
            atomicAdd(&ssq[col + 3], v.w * v.w);
        }
    }

    if (MODE == 1) {
        __syncthreads();
        if (tid < F) {
            atomicAdd(&sums[tid], ssum[tid]);
            atomicAdd(&sq[tid], ssq[tid]);
        }
    }
}

// ---------------------------------------------------------------------------
extern "C" void kernel_launch(void* const* d_in, const int* in_sizes, int n_in,
                              void* d_out, int out_size) {
    const float* x  = (const float*)d_in[0];
    const int*   ei = (const int*)d_in[1];
    const float* W0 = (const float*)d_in[2];
    const float* W1 = (const float*)d_in[3];
    const float* W2 = (const float*)d_in[4];
    const float* W3 = (const float*)d_in[5];
    float* out = (float*)d_out;

    float *pt, *pt2, *pu, *pc, *psum, *psq, *pmean, *pscl;
    cudaGetSymbolAddress((void**)&pt, g_t);
    cudaGetSymbolAddress((void**)&pt2, g_t2);
    cudaGetSymbolAddress((void**)&pu, g_u);
    cudaGetSymbolAddress((void**)&pc, g_c);
    cudaGetSymbolAddress((void**)&psum, g_sum);
    cudaGetSymbolAddress((void**)&psq, g_sq);
    cudaGetSymbolAddress((void**)&pmean, g_meanL);
    cudaGetSymbolAddress((void**)&pscl, g_sclL);

    const int gbE = (NE + 255) / 256;
    const int gbN = (NN + 255) / 256;
    const int gbG160 = (NN + 159) / 160;   // 313 blocks, BM=160
    const int gbG128 = (NN + 127) / 128;   // 391 blocks, BM=128 (k3)
    const int gbW = NN / 16;

    float* m0 = pmean + 0 * HID; float* s0 = pscl + 0 * HID;
    float* m1 = pmean + 1 * HID; float* s1 = pscl + 1 * HID;
    float* m2 = pmean + 2 * HID; float* s2 = pscl + 2 * HID;

    // dynamic smem: ws + dup A double buffer (BM-dependent) + stats
    const int xs160 = 2 * 16 * 160 * 8;  // 40960
    const int xs128 = 2 * 16 * 128 * 8;  // 32768
    const int sm0 = 128 * 98 * 4 + xs160 + 96 * 8 + 64;   // ~92 KB -> 2 CTAs
    const int sm1 = 96 * 98 * 4 + xs160 + 96 * 8 + 64;    // ~79 KB -> 2 CTAs
    const int sm3 = 96 * 42 * 4 + xs128 + 40 * 8 + 64;    // ~49 KB

    auto k0  = gemm_kernel<INC, HID, 10, 3, 16, 16, 0, 1>;
    auto k12 = gemm_kernel<HID, HID, 10, 3, 16, 16, 1, 0>;
    auto k3  = gemm_kernel<HID, OUTC, 2, 5, 4, 64, 1, 0>;
    cudaFuncSetAttribute(k0, cudaFuncAttributeMaxDynamicSharedMemorySize, sm0);
    cudaFuncSetAttribute(k12, cudaFuncAttributeMaxDynamicSharedMemorySize, sm1);
    cudaFuncSetAttribute(k3, cudaFuncAttributeMaxDynamicSharedMemorySize, sm3);

    // ---- prep + layer-0 GEMM (slot 4 for the ncu capture window) ----
    zero_prep_kernel<<<gbN, 256>>>();
    cnt_kernel<<<gbE, 256>>>(ei);
    scan1_kernel<<<SCB, 256>>>();
    k0<<<gbG160, 256, sm0>>>(x, W0, pt, nullptr, nullptr, nullptr, 1.f,
                             psum + 0 * HID, psq + 0 * HID);
    scan2_kernel<<<1, 256>>>();
    scan3_kernel<<<SCB, 256>>>();
    fill_kernel<<<gbE, 256>>>(ei);
    bn_final_kernel<<<1, HID>>>(psum + 0 * HID, psq + 0 * HID, m0, s0);

    // ---- layer 1 (beta = 0.5) ----
    k12<<<gbG160, 256, sm1>>>(pt, W1, pt2, pt, m0, s0, 0.5f, nullptr, nullptr);
    gather_kernel<HID, 1><<<gbW, 512>>>(pt2, pu, pt, m0, s0, psum + 1 * HID, psq + 1 * HID);
    bn_final_kernel<<<1, HID>>>(psum + 1 * HID, psq + 1 * HID, m1, s1);

    // ---- layer 2 (beta = 0.25) ----
    k12<<<gbG160, 256, sm1>>>(pu, W2, pt2, pu, m1, s1, 0.25f, nullptr, nullptr);
    gather_kernel<HID, 1><<<gbW, 512>>>(pt2, pu, pt, m0, s0, psum + 2 * HID, psq + 2 * HID);
    bn_final_kernel<<<1, HID>>>(psum + 2 * HID, psq + 2 * HID, m2, s2);

    // ---- final: c = bn2relu(u) @ W3^T ; out = spmm(c) ----
    k3<<<gbG128, 256, sm3>>>(pu, W3, pc, nullptr, m2, s2, 1.f, nullptr, nullptr);
    gather_kernel<OUTC, 0><<<gbW, 512>>>(pc, out, nullptr, nullptr, nullptr, nullptr, nullptr);
}

// round 10
// speedup vs baseline: 1.6037x; 1.1653x over previous
#include <cuda_runtime.h>
#include <cuda_bf16.h>

#define NN 50000
#define NE 800000
#define INC 128
#define HID 96
#define OUTC 40
#define SCB 196   // scan blocks: 196*256 = 50176 >= NN

__device__ float g_dinv[NN];
__device__ float g_selfw[NN];
__device__ int   g_cnt[NN];
__device__ int   g_fill[NN];
__device__ int   g_rowptr[NN + 1];
__device__ int   g_bsum[256];
__device__ int   g_boff[256];
__device__ int   g_col[NE];
__device__ float g_ew[NE];
__device__ float g_t [NN * HID];
__device__ float g_t2[NN * HID];
__device__ float g_u [NN * HID];
__device__ float g_c [NN * OUTC];
__device__ float g_sum[3 * HID];
__device__ float g_sq [3 * HID];

// ---------------------------------------------------------------------------
// helpers
// ---------------------------------------------------------------------------
typedef unsigned long long ull;

__device__ __forceinline__ void ffma2(ull& acc, ull a2, ull b2) {
    asm("fma.rn.f32x2 %0, %1, %2, %3;" : "=l"(acc) : "l"(a2), "l"(b2), "l"(acc));
}
__device__ __forceinline__ float2 unpack2(ull v) {
    float2 r;
    asm("mov.b64 {%0, %1}, %2;" : "=f"(r.x), "=f"(r.y) : "l"(v));
    return r;
}
__device__ __forceinline__ unsigned su32(const void* p) {
    return (unsigned)__cvta_generic_to_shared(p);
}
__device__ __forceinline__ ull lds64(unsigned a) {
    ull v;
    asm volatile("ld.shared.b64 %0, [%1];" : "=l"(v) : "r"(a));
    return v;
}

// ---------------------------------------------------------------------------
// Prep
// ---------------------------------------------------------------------------
__global__ void zero_prep_kernel() {
    int i = blockIdx.x * blockDim.x + threadIdx.x;
    if (i < NN) { g_cnt[i] = 0; g_fill[i] = 0; }
    if (i < 3 * HID) { g_sum[i] = 0.f; g_sq[i] = 0.f; }
}

__global__ void cnt_kernel(const int* __restrict__ ei) {
    int e = blockIdx.x * blockDim.x + threadIdx.x;
    if (e >= NE) return;
    int s = ei[e];
    int d = ei[NE + e];
    if (s != d) atomicAdd(&g_cnt[d], 1);
}

__global__ void scan1_kernel() {
    __shared__ int sh[256];
    int i = blockIdx.x * 256 + threadIdx.x;
    sh[threadIdx.x] = (i < NN) ? g_cnt[i] : 0;
    __syncthreads();
    for (int o = 128; o > 0; o >>= 1) {
        if (threadIdx.x < o) sh[threadIdx.x] += sh[threadIdx.x + o];
        __syncthreads();
    }
    if (threadIdx.x == 0) g_bsum[blockIdx.x] = sh[0];
}

__global__ void scan2_kernel() {
    __shared__ int sh[256];
    int t = threadIdx.x;
    int v = (t < SCB) ? g_bsum[t] : 0;
    sh[t] = v;
    __syncthreads();
    for (int o = 1; o < 256; o <<= 1) {
        int add = (t >= o) ? sh[t - o] : 0;
        __syncthreads();
        sh[t] += add;
        __syncthreads();
    }
    if (t < SCB) g_boff[t] = sh[t] - v;
    if (t == 255) g_rowptr[NN] = sh[255];
}

__global__ void scan3_kernel() {
    __shared__ int sh[256];
    int t = threadIdx.x;
    int i = blockIdx.x * 256 + t;
    int v = (i < NN) ? g_cnt[i] : 0;
    sh[t] = v;
    __syncthreads();
    for (int o = 1; o < 256; o <<= 1) {
        int add = (t >= o) ? sh[t - o] : 0;
        __syncthreads();
        sh[t] += add;
        __syncthreads();
    }
    if (i < NN) {
        g_rowptr[i] = g_boff[blockIdx.x] + sh[t] - v;
        float d = (float)v + 1.f;
        g_dinv[i]  = rsqrtf(d);
        g_selfw[i] = 1.f / d;
    }
}

__global__ void fill_kernel(const int* __restrict__ ei) {
    int e = blockIdx.x * blockDim.x + threadIdx.x;
    if (e >= NE) return;
    int s = ei[e];
    int d = ei[NE + e];
    if (s == d) return;
    int pos = g_rowptr[d] + atomicAdd(&g_fill[d], 1);
    g_col[pos] = s;
    g_ew[pos] = g_dinv[s] * g_dinv[d];
}

// ---------------------------------------------------------------------------
// BN param helper: mean/scl from raw sums
// ---------------------------------------------------------------------------
__device__ __forceinline__ void bn_params(float sum, float sq, float& m, float& s) {
    const float invN = 1.f / (float)NN;
    m = sum * invN;
    float v = sq * invN - m * m;
    s = rsqrtf(v + 1e-5f);
}

// ---------------------------------------------------------------------------
// SGEMM (exact R6 mainloop): W SMEM-resident (K-major, stride NOUT+2), A tile
// DUPLICATED (float2(v,v)) + double-buffered. Inner loop pure LDS.64 + FFMA2.
// NORM=1: BN params computed in-block from statsInSum/statsInSq (raw sums),
//         applied to A staging and blend operand.
// STATS=1: fused column sums/sumsq of Out -> statsOutSum/statsOutSq.
// Requires: TX*TY=256, TM*TY=128, TX*2*TNP=NOUT, K%16==0.
// ---------------------------------------------------------------------------
template <int K, int NOUT, int TM, int TNP, int TX, int TY, int NORM, int STATS>
__global__ void __launch_bounds__(256)
gemm_kernel(const float* __restrict__ A,
            const float* __restrict__ Wg,
            float* __restrict__ Out,
            const float* __restrict__ blendSrc,
            const float* __restrict__ statsInSum,
            const float* __restrict__ statsInSq,
            float beta,
            float* __restrict__ statsOutSum,
            float* __restrict__ statsOutSq) {
    constexpr int BM = TM * TY;         // 128
    constexpr int NT = TX * TY;         // 256
    constexpr int WSTR = NOUT + 2;
    constexpr int NC = K / 16;
    constexpr int CN = 2 * TNP;

    extern __shared__ char smem[];
    float*  ws      = (float*)smem;                                  // K*WSTR
    float2* xs      = (float2*)(smem + K * WSTR * 4);                // 2*16*BM
    float*  ssum    = (float*)(smem + K * WSTR * 4 + 2 * 16 * BM * 8);
    float*  ssq     = ssum + NOUT;
    float*  sm_mean = ssq + NOUT;                                    // K (NORM)
    float*  sm_scl  = sm_mean + (NORM ? K : 0);

    int tid = threadIdx.x;
    int tx = tid % TX;
    int ty = tid / TX;
    int rowbase = blockIdx.x * BM;

    if (STATS) {
        for (int i = tid; i < NOUT; i += NT) { ssum[i] = 0.f; ssq[i] = 0.f; }
    }
    if (NORM) {
        for (int i = tid; i < K; i += NT) {
            float m, s;
            bn_params(statsInSum[i], statsInSq[i], m, s);
            sm_mean[i] = m;
            sm_scl[i] = s;
        }
        __syncthreads();   // sm_mean/sm_scl ready before prologue staging
    }

    // ---- load W transposed into SMEM (once) ----
    constexpr int K4 = K / 4;
    for (int i = tid; i < NOUT * K4; i += NT) {
        int n = i / K4, q = i % K4;
        float4 w = __ldg((const float4*)&Wg[(size_t)n * K + q * 4]);
        ws[(q * 4 + 0) * WSTR + n] = w.x;
        ws[(q * 4 + 1) * WSTR + n] = w.y;
        ws[(q * 4 + 2) * WSTR + n] = w.z;
        ws[(q * 4 + 3) * WSTR + n] = w.w;
    }

    auto ldA = [&](int ch, int i) -> float4 {
        int r = i >> 2, c4 = (i & 3) * 4;
        int row = rowbase + r;
        int k = ch * 16 + c4;
        float4 v = (row < NN) ? __ldg((const float4*)&A[(size_t)row * K + k])
                              : make_float4(0.f, 0.f, 0.f, 0.f);
        if (NORM) {
            float4 m = ((const float4*)sm_mean)[k >> 2];
            float4 s = ((const float4*)sm_scl)[k >> 2];
            v.x = fmaxf((v.x - m.x) * s.x, 0.f);
            v.y = fmaxf((v.y - m.y) * s.y, 0.f);
            v.z = fmaxf((v.z - m.z) * s.z, 0.f);
            v.w = fmaxf((v.w - m.w) * s.w, 0.f);
        }
        return v;
    };
    auto stA = [&](int buf, int i, float4 v) {
        int r = i >> 2, c4 = (i & 3) * 4;
        float2* base = &xs[(size_t)(buf * 16) * BM + r];
        base[(c4 + 0) * BM] = make_float2(v.x, v.x);
        base[(c4 + 1) * BM] = make_float2(v.y, v.y);
        base[(c4 + 2) * BM] = make_float2(v.z, v.z);
        base[(c4 + 3) * BM] = make_float2(v.w, v.w);
    };

    stA(0, tid, ldA(0, tid));
    stA(0, tid + 256, ldA(0, tid + 256));
    __syncthreads();

    ull acc2[TM][TNP];
#pragma unroll
    for (int r = 0; r < TM; r++)
#pragma unroll
        for (int c = 0; c < TNP; c++) acc2[r][c] = 0ull;

    unsigned athr = su32(xs) + (unsigned)(ty * TM) * 8u;
    unsigned bthr = su32(ws) + (unsigned)(tx * CN) * 4u;

#pragma unroll 2
    for (int ch = 0; ch < NC; ch++) {
        bool pre = (ch + 1 < NC);
        float4 p0, p1;
        if (pre) { p0 = ldA(ch + 1, tid); p1 = ldA(ch + 1, tid + 256); }

        unsigned abase = athr + (unsigned)((ch & 1) * 16 * BM) * 8u;
        unsigned bbase = bthr + (unsigned)(ch * 16 * WSTR) * 4u;
#pragma unroll
        for (int kk = 0; kk < 16; kk++) {
            ull a2[TM], b2[TNP];
#pragma unroll
            for (int r = 0; r < TM; r++)
                a2[r] = lds64(abase + (unsigned)(kk * BM + r) * 8u);
#pragma unroll
            for (int c = 0; c < TNP; c++)
                b2[c] = lds64(bbase + (unsigned)(kk * WSTR) * 4u + (unsigned)c * 8u);
#pragma unroll
            for (int r = 0; r < TM; r++)
#pragma unroll
                for (int c = 0; c < TNP; c++) ffma2(acc2[r][c], a2[r], b2[c]);
        }

        if (pre) {
            int buf = (ch + 1) & 1;
            stA(buf, tid, p0);
            stA(buf, tid + 256, p1);
        }
        __syncthreads();
    }

    // ---- epilogue ----
    float colsum[CN], colsq[CN];
    if (STATS) {
#pragma unroll
        for (int c = 0; c < CN; c++) { colsum[c] = 0.f; colsq[c] = 0.f; }
    }

#pragma unroll
    for (int r = 0; r < TM; r++) {
        int row = rowbase + ty * TM + r;
        if (row >= NN) continue;
#pragma unroll
        for (int c = 0; c < TNP; c++) {
            int col = tx * CN + 2 * c;
            float2 v = unpack2(acc2[r][c]);
            if (beta != 1.f) {
                float2 b = *(const float2*)&blendSrc[(size_t)row * NOUT + col];
                if (NORM) {
                    b.x = fmaxf((b.x - sm_mean[col + 0]) * sm_scl[col + 0], 0.f);
                    b.y = fmaxf((b.y - sm_mean[col + 1]) * sm_scl[col + 1], 0.f);
                }
                v.x = beta * v.x + (1.f - beta) * b.x;
                v.y = beta * v.y + (1.f - beta) * b.y;
            }
            *(float2*)&Out[(size_t)row * NOUT + col] = v;
            if (STATS) {
                colsum[2 * c] += v.x;     colsq[2 * c] += v.x * v.x;
                colsum[2 * c + 1] += v.y; colsq[2 * c + 1] += v.y * v.y;
            }
        }
    }

    if (STATS) {
#pragma unroll
        for (int c = 0; c < CN; c++) {
            atomicAdd(&ssum[tx * CN + c], colsum[c]);
            atomicAdd(&ssq[tx * CN + c], colsq[c]);
        }
        __syncthreads();
        for (int i = tid; i < NOUT; i += NT) {
            atomicAdd(&statsOutSum[i], ssum[i]);
            atomicAdd(&statsOutSq[i], ssq[i]);
        }
    }
}

// ---------------------------------------------------------------------------
// CSR gather SpMM, warp per node, float4 lanes, edge loop unrolled x4.
// MODE 1: Y = 0.9*(sum + selfw*X) + 0.1*relu(bn0(h0raw)); bn0 params computed
//         in-block from sums0/sq0; fused col stats of Y -> sumsOut/sqOut.
// MODE 0: Y = sum + selfw*X
// Grid covers exactly NN warps.
// ---------------------------------------------------------------------------
template <int F, int MODE>
__global__ void gather_kernel(const float* __restrict__ X, float* __restrict__ Y,
                              const float* __restrict__ h0raw,
                              const float* __restrict__ sums0,
                              const float* __restrict__ sq0,
                              float* __restrict__ sumsOut,
                              float* __restrict__ sqOut) {
    constexpr int NV = F / 4;
    __shared__ __align__(16) float ssum[HID];
    __shared__ __align__(16) float ssq[HID];
    __shared__ __align__(16) float sm_m[HID];
    __shared__ __align__(16) float sm_s[HID];
    int tid = threadIdx.x;
    if (MODE == 1) {
        if (tid < F) {
            ssum[tid] = 0.f;
            ssq[tid] = 0.f;
            float m, s;
            bn_params(sums0[tid], sq0[tid], m, s);
            sm_m[tid] = m;
            sm_s[tid] = s;
        }
        __syncthreads();
    }
    int node = blockIdx.x * (blockDim.x >> 5) + (tid >> 5);
    int lane = tid & 31;
    bool act = lane < NV;
    const float4* Xv = (const float4*)X;

    float4 sum = make_float4(0.f, 0.f, 0.f, 0.f);
    int p   = g_rowptr[node];
    int end = g_rowptr[node + 1];

    for (; p + 4 <= end; p += 4) {
        int   c0 = __ldg(&g_col[p]),     c1 = __ldg(&g_col[p + 1]);
        int   c2 = __ldg(&g_col[p + 2]), c3 = __ldg(&g_col[p + 3]);
        float w0 = __ldg(&g_ew[p]),      w1 = __ldg(&g_ew[p + 1]);
        float w2 = __ldg(&g_ew[p + 2]),  w3 = __ldg(&g_ew[p + 3]);
        if (act) {
            float4 v0 = __ldg(&Xv[(size_t)c0 * NV + lane]);
            float4 v1 = __ldg(&Xv[(size_t)c1 * NV + lane]);
            float4 v2 = __ldg(&Xv[(size_t)c2 * NV + lane]);
            float4 v3 = __ldg(&Xv[(size_t)c3 * NV + lane]);
            sum.x += w0 * v0.x + w1 * v1.x + w2 * v2.x + w3 * v3.x;
            sum.y += w0 * v0.y + w1 * v1.y + w2 * v2.y + w3 * v3.y;
            sum.z += w0 * v0.z + w1 * v1.z + w2 * v2.z + w3 * v3.z;
            sum.w += w0 * v0.w + w1 * v1.w + w2 * v2.w + w3 * v3.w;
        }
    }
    for (; p < end; p++) {
        int c = __ldg(&g_col[p]);
        float w = __ldg(&g_ew[p]);
        if (act) {
            float4 v = __ldg(&Xv[(size_t)c * NV + lane]);
            sum.x += w * v.x; sum.y += w * v.y;
            sum.z += w * v.z; sum.w += w * v.w;
        }
    }

    if (act) {
        float sw = g_selfw[node];
        float4 xv = __ldg(&Xv[(size_t)node * NV + lane]);
        float4 v;
        v.x = sum.x + sw * xv.x;
        v.y = sum.y + sw * xv.y;
        v.z = sum.z + sw * xv.z;
        v.w = sum.w + sw * xv.w;
        if (MODE == 1) {
            float4 m  = ((const float4*)sm_m)[lane];
            float4 s  = ((const float4*)sm_s)[lane];
            float4 hr = __ldg(&((const float4*)h0raw)[(size_t)node * NV + lane]);
            v.x = 0.9f * v.x + 0.1f * fmaxf((hr.x - m.x) * s.x, 0.f);
            v.y = 0.9f * v.y + 0.1f * fmaxf((hr.y - m.y) * s.y, 0.f);
            v.z = 0.9f * v.z + 0.1f * fmaxf((hr.z - m.z) * s.z, 0.f);
            v.w = 0.9f * v.w + 0.1f * fmaxf((hr.w - m.w) * s.w, 0.f);
        }
        ((float4*)Y)[(size_t)node * NV + lane] = v;
        if (MODE == 1) {
            int col = lane * 4;
            atomicAdd(&ssum[col + 0], v.x);
            atomicAdd(&ssum[col + 1], v.y);
            atomicAdd(&ssum[col + 2], v.z);
            atomicAdd(&ssum[col + 3], v.w);
            atomicAdd(&ssq[col + 0], v.x * v.x);
            atomicAdd(&ssq[col + 1], v.y * v.y);
            atomicAdd(&ssq[col + 2], v.z * v.z);
            atomicAdd(&ssq[col + 3], v.w * v.w);
        }
    }

    if (MODE == 1) {
        __syncthreads();
        if (tid < F) {
            atomicAdd(&sumsOut[tid], ssum[tid]);
            atomicAdd(&sqOut[tid], ssq[tid]);
        }
    }
}

// ---------------------------------------------------------------------------
extern "C" void kernel_launch(void* const* d_in, const int* in_sizes, int n_in,
                              void* d_out, int out_size) {
    const float* x  = (const float*)d_in[0];
    const int*   ei = (const int*)d_in[1];
    const float* W0 = (const float*)d_in[2];
    const float* W1 = (const float*)d_in[3];
    const float* W2 = (const float*)d_in[4];
    const float* W3 = (const float*)d_in[5];
    float* out = (float*)d_out;

    float *pt, *pt2, *pu, *pc, *psum, *psq;
    cudaGetSymbolAddress((void**)&pt, g_t);
    cudaGetSymbolAddress((void**)&pt2, g_t2);
    cudaGetSymbolAddress((void**)&pu, g_u);
    cudaGetSymbolAddress((void**)&pc, g_c);
    cudaGetSymbolAddress((void**)&psum, g_sum);
    cudaGetSymbolAddress((void**)&psq, g_sq);

    const int gbE = (NE + 255) / 256;
    const int gbN = (NN + 255) / 256;
    const int gbG = (NN + 127) / 128;   // 391 blocks, BM=128
    const int gbW = NN / 16;

    float* s0m = psum + 0 * HID; float* s0q = psq + 0 * HID;
    float* s1m = psum + 1 * HID; float* s1q = psq + 1 * HID;
    float* s2m = psum + 2 * HID; float* s2q = psq + 2 * HID;

    // dynamic smem: ws + dup A double buffer + stats + (NORM) mean/scl
    const int xsBytes = 2 * 16 * 128 * 8;  // 32768
    const int sm0 = 128 * 98 * 4 + xsBytes + 96 * 8 + 64;            // ~83.9 KB
    const int sm1 = 96 * 98 * 4 + xsBytes + 96 * 8 + 96 * 8 + 64;    // ~72 KB
    const int sm3 = 96 * 42 * 4 + xsBytes + 40 * 8 + 96 * 8 + 64;    // ~50 KB

    auto k0  = gemm_kernel<INC, HID, 8, 3, 16, 16, 0, 1>;
    auto k12 = gemm_kernel<HID, HID, 8, 3, 16, 16, 1, 0>;
    auto k3  = gemm_kernel<HID, OUTC, 2, 5, 4, 64, 1, 0>;
    cudaFuncSetAttribute(k0, cudaFuncAttributeMaxDynamicSharedMemorySize, sm0);
    cudaFuncSetAttribute(k12, cudaFuncAttributeMaxDynamicSharedMemorySize, sm1);
    cudaFuncSetAttribute(k3, cudaFuncAttributeMaxDynamicSharedMemorySize, sm3);

    // ---- prep + layer-0 GEMM ----
    zero_prep_kernel<<<gbN, 256>>>();
    cnt_kernel<<<gbE, 256>>>(ei);
    scan1_kernel<<<SCB, 256>>>();
    k0<<<gbG, 256, sm0>>>(x, W0, pt, nullptr, nullptr, nullptr, 1.f, s0m, s0q);
    scan2_kernel<<<1, 256>>>();
    scan3_kernel<<<SCB, 256>>>();
    fill_kernel<<<gbE, 256>>>(ei);

    // ---- layer 1 (beta = 0.5): BN0 params computed in-block from s0 ----
    k12<<<gbG, 256, sm1>>>(pt, W1, pt2, pt, s0m, s0q, 0.5f, nullptr, nullptr);
    gather_kernel<HID, 1><<<gbW, 512>>>(pt2, pu, pt, s0m, s0q, s1m, s1q);

    // ---- layer 2 (beta = 0.25): BN1 params from s1 ----
    k12<<<gbG, 256, sm1>>>(pu, W2, pt2, pu, s1m, s1q, 0.25f, nullptr, nullptr);
    gather_kernel<HID, 1><<<gbW, 512>>>(pt2, pu, pt, s0m, s0q, s2m, s2q);

    // ---- final: c = bn2relu(u) @ W3^T ; out = spmm(c) ----
    k3<<<gbG, 256, sm3>>>(pu, W3, pc, nullptr, s2m, s2q, 1.f, nullptr, nullptr);
    gather_kernel<OUTC, 0><<<gbW, 512>>>(pc, out, nullptr, nullptr, nullptr, nullptr, nullptr);
}

// round 11
// speedup vs baseline: 1.6959x; 1.0575x over previous
#include <cuda_runtime.h>
#include <cuda_bf16.h>

#define NN 50000
#define NE 800000
#define INC 128
#define HID 96
#define OUTC 40
#define SCB 196   // scan blocks: 196*256 = 50176 >= NN

__device__ float g_dinv[NN];
__device__ float g_selfw[NN];
__device__ int   g_cnt[NN];
__device__ int   g_fill[NN];
__device__ int   g_rowptr[NN + 1];
__device__ int   g_bsum[256];
__device__ int   g_boff[256];
__device__ int   g_col[NE];
__device__ float g_ew[NE];
__device__ float g_t [NN * HID];
__device__ float g_t2[NN * HID];
__device__ float g_u [NN * HID];
__device__ float g_c [NN * OUTC];
__device__ float g_sum[3 * HID];
__device__ float g_sq [3 * HID];

// ---------------------------------------------------------------------------
// helpers
// ---------------------------------------------------------------------------
typedef unsigned long long ull;

__device__ __forceinline__ void ffma2(ull& acc, ull a2, ull b2) {
    asm("fma.rn.f32x2 %0, %1, %2, %3;" : "=l"(acc) : "l"(a2), "l"(b2), "l"(acc));
}
__device__ __forceinline__ float2 unpack2(ull v) {
    float2 r;
    asm("mov.b64 {%0, %1}, %2;" : "=f"(r.x), "=f"(r.y) : "l"(v));
    return r;
}
__device__ __forceinline__ unsigned su32(const void* p) {
    return (unsigned)__cvta_generic_to_shared(p);
}
__device__ __forceinline__ ull lds64(unsigned a) {
    ull v;
    asm volatile("ld.shared.b64 %0, [%1];" : "=l"(v) : "r"(a));
    return v;
}

// ---------------------------------------------------------------------------
// Prep
// ---------------------------------------------------------------------------
__global__ void zero_prep_kernel() {
    int i = blockIdx.x * blockDim.x + threadIdx.x;
    if (i < NN) { g_cnt[i] = 0; g_fill[i] = 0; }
    if (i < 3 * HID) { g_sum[i] = 0.f; g_sq[i] = 0.f; }
}

__global__ void cnt_kernel(const int* __restrict__ ei) {
    int e = blockIdx.x * blockDim.x + threadIdx.x;
    if (e >= NE) return;
    int s = ei[e];
    int d = ei[NE + e];
    if (s != d) atomicAdd(&g_cnt[d], 1);
}

__global__ void scan1_kernel() {
    __shared__ int sh[256];
    int i = blockIdx.x * 256 + threadIdx.x;
    sh[threadIdx.x] = (i < NN) ? g_cnt[i] : 0;
    __syncthreads();
    for (int o = 128; o > 0; o >>= 1) {
        if (threadIdx.x < o) sh[threadIdx.x] += sh[threadIdx.x + o];
        __syncthreads();
    }
    if (threadIdx.x == 0) g_bsum[blockIdx.x] = sh[0];
}

__global__ void scan2_kernel() {
    __shared__ int sh[256];
    int t = threadIdx.x;
    int v = (t < SCB) ? g_bsum[t] : 0;
    sh[t] = v;
    __syncthreads();
    for (int o = 1; o < 256; o <<= 1) {
        int add = (t >= o) ? sh[t - o] : 0;
        __syncthreads();
        sh[t] += add;
        __syncthreads();
    }
    if (t < SCB) g_boff[t] = sh[t] - v;
    if (t == 255) g_rowptr[NN] = sh[255];
}

__global__ void scan3_kernel() {
    __shared__ int sh[256];
    int t = threadIdx.x;
    int i = blockIdx.x * 256 + t;
    int v = (i < NN) ? g_cnt[i] : 0;
    sh[t] = v;
    __syncthreads();
    for (int o = 1; o < 256; o <<= 1) {
        int add = (t >= o) ? sh[t - o] : 0;
        __syncthreads();
        sh[t] += add;
        __syncthreads();
    }
    if (i < NN) {
        g_rowptr[i] = g_boff[blockIdx.x] + sh[t] - v;
        float d = (float)v + 1.f;
        g_dinv[i]  = rsqrtf(d);
        g_selfw[i] = 1.f / d;
    }
}

__global__ void fill_kernel(const int* __restrict__ ei) {
    int e = blockIdx.x * blockDim.x + threadIdx.x;
    if (e >= NE) return;
    int s = ei[e];
    int d = ei[NE + e];
    if (s == d) return;
    int pos = g_rowptr[d] + atomicAdd(&g_fill[d], 1);
    g_col[pos] = s;
    g_ew[pos] = g_dinv[s] * g_dinv[d];
}

// ---------------------------------------------------------------------------
// BN param helper: mean/scl from raw sums
// ---------------------------------------------------------------------------
__device__ __forceinline__ void bn_params(float sum, float sq, float& m, float& s) {
    const float invN = 1.f / (float)NN;
    m = sum * invN;
    float v = sq * invN - m * m;
    s = rsqrtf(v + 1e-5f);
}

// ---------------------------------------------------------------------------
// SGEMM (exact R6 mainloop): W SMEM-resident (K-major, stride NOUT+2), A tile
// DUPLICATED (float2(v,v)) + double-buffered. Inner loop pure LDS.64 + FFMA2.
// NORM=1: BN params computed in-block from statsInSum/statsInSq.
// STATS=1: fused column sums/sumsq of Out.
// Requires: TX*TY=256, TM*TY=128, TX*2*TNP=NOUT, K%16==0.
// ---------------------------------------------------------------------------
template <int K, int NOUT, int TM, int TNP, int TX, int TY, int NORM, int STATS>
__global__ void __launch_bounds__(256)
gemm_kernel(const float* __restrict__ A,
            const float* __restrict__ Wg,
            float* __restrict__ Out,
            const float* __restrict__ blendSrc,
            const float* __restrict__ statsInSum,
            const float* __restrict__ statsInSq,
            float beta,
            float* __restrict__ statsOutSum,
            float* __restrict__ statsOutSq) {
    constexpr int BM = TM * TY;         // 128
    constexpr int NT = TX * TY;         // 256
    constexpr int WSTR = NOUT + 2;
    constexpr int NC = K / 16;
    constexpr int CN = 2 * TNP;

    extern __shared__ char smem[];
    float*  ws      = (float*)smem;                                  // K*WSTR
    float2* xs      = (float2*)(smem + K * WSTR * 4);                // 2*16*BM
    float*  ssum    = (float*)(smem + K * WSTR * 4 + 2 * 16 * BM * 8);
    float*  ssq     = ssum + NOUT;
    float*  sm_mean = ssq + NOUT;                                    // K (NORM)
    float*  sm_scl  = sm_mean + (NORM ? K : 0);

    int tid = threadIdx.x;
    int tx = tid % TX;
    int ty = tid / TX;
    int rowbase = blockIdx.x * BM;

    if (STATS) {
        for (int i = tid; i < NOUT; i += NT) { ssum[i] = 0.f; ssq[i] = 0.f; }
    }
    if (NORM) {
        for (int i = tid; i < K; i += NT) {
            float m, s;
            bn_params(statsInSum[i], statsInSq[i], m, s);
            sm_mean[i] = m;
            sm_scl[i] = s;
        }
        __syncthreads();
    }

    // ---- load W transposed into SMEM (once) ----
    constexpr int K4 = K / 4;
    for (int i = tid; i < NOUT * K4; i += NT) {
        int n = i / K4, q = i % K4;
        float4 w = __ldg((const float4*)&Wg[(size_t)n * K + q * 4]);
        ws[(q * 4 + 0) * WSTR + n] = w.x;
        ws[(q * 4 + 1) * WSTR + n] = w.y;
        ws[(q * 4 + 2) * WSTR + n] = w.z;
        ws[(q * 4 + 3) * WSTR + n] = w.w;
    }

    auto ldA = [&](int ch, int i) -> float4 {
        int r = i >> 2, c4 = (i & 3) * 4;
        int row = rowbase + r;
        int k = ch * 16 + c4;
        float4 v = (row < NN) ? __ldg((const float4*)&A[(size_t)row * K + k])
                              : make_float4(0.f, 0.f, 0.f, 0.f);
        if (NORM) {
            float4 m = ((const float4*)sm_mean)[k >> 2];
            float4 s = ((const float4*)sm_scl)[k >> 2];
            v.x = fmaxf((v.x - m.x) * s.x, 0.f);
            v.y = fmaxf((v.y - m.y) * s.y, 0.f);
            v.z = fmaxf((v.z - m.z) * s.z, 0.f);
            v.w = fmaxf((v.w - m.w) * s.w, 0.f);
        }
        return v;
    };
    auto stA = [&](int buf, int i, float4 v) {
        int r = i >> 2, c4 = (i & 3) * 4;
        float2* base = &xs[(size_t)(buf * 16) * BM + r];
        base[(c4 + 0) * BM] = make_float2(v.x, v.x);
        base[(c4 + 1) * BM] = make_float2(v.y, v.y);
        base[(c4 + 2) * BM] = make_float2(v.z, v.z);
        base[(c4 + 3) * BM] = make_float2(v.w, v.w);
    };

    stA(0, tid, ldA(0, tid));
    stA(0, tid + 256, ldA(0, tid + 256));
    __syncthreads();

    ull acc2[TM][TNP];
#pragma unroll
    for (int r = 0; r < TM; r++)
#pragma unroll
        for (int c = 0; c < TNP; c++) acc2[r][c] = 0ull;

    unsigned athr = su32(xs) + (unsigned)(ty * TM) * 8u;
    unsigned bthr = su32(ws) + (unsigned)(tx * CN) * 4u;

#pragma unroll 2
    for (int ch = 0; ch < NC; ch++) {
        bool pre = (ch + 1 < NC);
        float4 p0, p1;
        if (pre) { p0 = ldA(ch + 1, tid); p1 = ldA(ch + 1, tid + 256); }

        unsigned abase = athr + (unsigned)((ch & 1) * 16 * BM) * 8u;
        unsigned bbase = bthr + (unsigned)(ch * 16 * WSTR) * 4u;
#pragma unroll
        for (int kk = 0; kk < 16; kk++) {
            ull a2[TM], b2[TNP];
#pragma unroll
            for (int r = 0; r < TM; r++)
                a2[r] = lds64(abase + (unsigned)(kk * BM + r) * 8u);
#pragma unroll
            for (int c = 0; c < TNP; c++)
                b2[c] = lds64(bbase + (unsigned)(kk * WSTR) * 4u + (unsigned)c * 8u);
#pragma unroll
            for (int r = 0; r < TM; r++)
#pragma unroll
                for (int c = 0; c < TNP; c++) ffma2(acc2[r][c], a2[r], b2[c]);
        }

        if (pre) {
            int buf = (ch + 1) & 1;
            stA(buf, tid, p0);
            stA(buf, tid + 256, p1);
        }
        __syncthreads();
    }

    // ---- epilogue ----
    float colsum[CN], colsq[CN];
    if (STATS) {
#pragma unroll
        for (int c = 0; c < CN; c++) { colsum[c] = 0.f; colsq[c] = 0.f; }
    }

#pragma unroll
    for (int r = 0; r < TM; r++) {
        int row = rowbase + ty * TM + r;
        if (row >= NN) continue;
#pragma unroll
        for (int c = 0; c < TNP; c++) {
            int col = tx * CN + 2 * c;
            float2 v = unpack2(acc2[r][c]);
            if (beta != 1.f) {
                float2 b = *(const float2*)&blendSrc[(size_t)row * NOUT + col];
                if (NORM) {
                    b.x = fmaxf((b.x - sm_mean[col + 0]) * sm_scl[col + 0], 0.f);
                    b.y = fmaxf((b.y - sm_mean[col + 1]) * sm_scl[col + 1], 0.f);
                }
                v.x = beta * v.x + (1.f - beta) * b.x;
                v.y = beta * v.y + (1.f - beta) * b.y;
            }
            *(float2*)&Out[(size_t)row * NOUT + col] = v;
            if (STATS) {
                colsum[2 * c] += v.x;     colsq[2 * c] += v.x * v.x;
                colsum[2 * c + 1] += v.y; colsq[2 * c + 1] += v.y * v.y;
            }
        }
    }

    if (STATS) {
#pragma unroll
        for (int c = 0; c < CN; c++) {
            atomicAdd(&ssum[tx * CN + c], colsum[c]);
            atomicAdd(&ssq[tx * CN + c], colsq[c]);
        }
        __syncthreads();
        for (int i = tid; i < NOUT; i += NT) {
            atomicAdd(&statsOutSum[i], ssum[i]);
            atomicAdd(&statsOutSq[i], ssq[i]);
        }
    }
}

// ---------------------------------------------------------------------------
// CSR gather SpMM, warp per node, float4 lanes, edge loop unrolled x4.
// MODE 1: Y = 0.9*(sum + selfw*X) + 0.1*relu(bn0(h0raw)); fused col stats.
// MODE 0: Y = sum + selfw*X
// ---------------------------------------------------------------------------
template <int F, int MODE>
__global__ void gather_kernel(const float* __restrict__ X, float* __restrict__ Y,
                              const float* __restrict__ h0raw,
                              const float* __restrict__ sums0,
                              const float* __restrict__ sq0,
                              float* __restrict__ sumsOut,
                              float* __restrict__ sqOut) {
    constexpr int NV = F / 4;
    __shared__ __align__(16) float ssum[HID];
    __shared__ __align__(16) float ssq[HID];
    __shared__ __align__(16) float sm_m[HID];
    __shared__ __align__(16) float sm_s[HID];
    int tid = threadIdx.x;
    if (MODE == 1) {
        if (tid < F) {
            ssum[tid] = 0.f;
            ssq[tid] = 0.f;
            float m, s;
            bn_params(sums0[tid], sq0[tid], m, s);
            sm_m[tid] = m;
            sm_s[tid] = s;
        }
        __syncthreads();
    }
    int node = blockIdx.x * (blockDim.x >> 5) + (tid >> 5);
    int lane = tid & 31;
    bool act = lane < NV;
    const float4* Xv = (const float4*)X;

    float4 sum = make_float4(0.f, 0.f, 0.f, 0.f);
    int p   = g_rowptr[node];
    int end = g_rowptr[node + 1];

    for (; p + 4 <= end; p += 4) {
        int   c0 = __ldg(&g_col[p]),     c1 = __ldg(&g_col[p + 1]);
        int   c2 = __ldg(&g_col[p + 2]), c3 = __ldg(&g_col[p + 3]);
        float w0 = __ldg(&g_ew[p]),      w1 = __ldg(&g_ew[p + 1]);
        float w2 = __ldg(&g_ew[p + 2]),  w3 = __ldg(&g_ew[p + 3]);
        if (act) {
            float4 v0 = __ldg(&Xv[(size_t)c0 * NV + lane]);
            float4 v1 = __ldg(&Xv[(size_t)c1 * NV + lane]);
            float4 v2 = __ldg(&Xv[(size_t)c2 * NV + lane]);
            float4 v3 = __ldg(&Xv[(size_t)c3 * NV + lane]);
            sum.x += w0 * v0.x + w1 * v1.x + w2 * v2.x + w3 * v3.x;
            sum.y += w0 * v0.y + w1 * v1.y + w2 * v2.y + w3 * v3.y;
            sum.z += w0 * v0.z + w1 * v1.z + w2 * v2.z + w3 * v3.z;
            sum.w += w0 * v0.w + w1 * v1.w + w2 * v2.w + w3 * v3.w;
        }
    }
    for (; p < end; p++) {
        int c = __ldg(&g_col[p]);
        float w = __ldg(&g_ew[p]);
        if (act) {
            float4 v = __ldg(&Xv[(size_t)c * NV + lane]);
            sum.x += w * v.x; sum.y += w * v.y;
            sum.z += w * v.z; sum.w += w * v.w;
        }
    }

    if (act) {
        float sw = g_selfw[node];
        float4 xv = __ldg(&Xv[(size_t)node * NV + lane]);
        float4 v;
        v.x = sum.x + sw * xv.x;
        v.y = sum.y + sw * xv.y;
        v.z = sum.z + sw * xv.z;
        v.w = sum.w + sw * xv.w;
        if (MODE == 1) {
            float4 m  = ((const float4*)sm_m)[lane];
            float4 s  = ((const float4*)sm_s)[lane];
            float4 hr = __ldg(&((const float4*)h0raw)[(size_t)node * NV + lane]);
            v.x = 0.9f * v.x + 0.1f * fmaxf((hr.x - m.x) * s.x, 0.f);
            v.y = 0.9f * v.y + 0.1f * fmaxf((hr.y - m.y) * s.y, 0.f);
            v.z = 0.9f * v.z + 0.1f * fmaxf((hr.z - m.z) * s.z, 0.f);
            v.w = 0.9f * v.w + 0.1f * fmaxf((hr.w - m.w) * s.w, 0.f);
        }
        ((float4*)Y)[(size_t)node * NV + lane] = v;
        if (MODE == 1) {
            int col = lane * 4;
            atomicAdd(&ssum[col + 0], v.x);
            atomicAdd(&ssum[col + 1], v.y);
            atomicAdd(&ssum[col + 2], v.z);
            atomicAdd(&ssum[col + 3], v.w);
            atomicAdd(&ssq[col + 0], v.x * v.x);
            atomicAdd(&ssq[col + 1], v.y * v.y);
            atomicAdd(&ssq[col + 2], v.z * v.z);
            atomicAdd(&ssq[col + 3], v.w * v.w);
        }
    }

    if (MODE == 1) {
        __syncthreads();
        if (tid < F) {
            atomicAdd(&sumsOut[tid], ssum[tid]);
            atomicAdd(&sqOut[tid], ssq[tid]);
        }
    }
}

// ---------------------------------------------------------------------------
extern "C" void kernel_launch(void* const* d_in, const int* in_sizes, int n_in,
                              void* d_out, int out_size) {
    const float* x  = (const float*)d_in[0];
    const int*   ei = (const int*)d_in[1];
    const float* W0 = (const float*)d_in[2];
    const float* W1 = (const float*)d_in[3];
    const float* W2 = (const float*)d_in[4];
    const float* W3 = (const float*)d_in[5];
    float* out = (float*)d_out;

    float *pt, *pt2, *pu, *pc, *psum, *psq;
    cudaGetSymbolAddress((void**)&pt, g_t);
    cudaGetSymbolAddress((void**)&pt2, g_t2);
    cudaGetSymbolAddress((void**)&pu, g_u);
    cudaGetSymbolAddress((void**)&pc, g_c);
    cudaGetSymbolAddress((void**)&psum, g_sum);
    cudaGetSymbolAddress((void**)&psq, g_sq);

    const int gbE = (NE + 255) / 256;
    const int gbN = (NN + 255) / 256;
    const int gbG = (NN + 127) / 128;
    const int gbW = NN / 16;

    float* s0m = psum + 0 * HID; float* s0q = psq + 0 * HID;
    float* s1m = psum + 1 * HID; float* s1q = psq + 1 * HID;
    float* s2m = psum + 2 * HID; float* s2q = psq + 2 * HID;

    const int xsBytes = 2 * 16 * 128 * 8;  // 32768
    const int sm0 = 128 * 98 * 4 + xsBytes + 96 * 8 + 64;
    const int sm1 = 96 * 98 * 4 + xsBytes + 96 * 8 + 96 * 8 + 64;
    const int sm3 = 96 * 42 * 4 + xsBytes + 40 * 8 + 96 * 8 + 64;

    auto k0  = gemm_kernel<INC, HID, 8, 3, 16, 16, 0, 1>;
    auto k12 = gemm_kernel<HID, HID, 8, 3, 16, 16, 1, 0>;
    auto k3  = gemm_kernel<HID, OUTC, 2, 5, 4, 64, 1, 0>;
    cudaFuncSetAttribute(k0, cudaFuncAttributeMaxDynamicSharedMemorySize, sm0);
    cudaFuncSetAttribute(k12, cudaFuncAttributeMaxDynamicSharedMemorySize, sm1);
    cudaFuncSetAttribute(k3, cudaFuncAttributeMaxDynamicSharedMemorySize, sm3);

    // Side stream + events for capture-safe fork/join. Created per call and
    // intentionally NOT destroyed (kernel_launch runs only ~2x: correctness +
    // capture; destroying mid-capture would invalidate the capture).
    cudaStream_t s2;
    cudaStreamCreateWithFlags(&s2, cudaStreamNonBlocking);
    cudaEvent_t eFork, eJoin;
    cudaEventCreateWithFlags(&eFork, cudaEventDisableTiming);
    cudaEventCreateWithFlags(&eJoin, cudaEventDisableTiming);

    // ---- zero (both branches depend on it) ----
    zero_prep_kernel<<<gbN, 256>>>();
    cudaEventRecord(eFork, 0);
    cudaStreamWaitEvent(s2, eFork, 0);

    // ---- branch A (stream s2): CSR build ----
    cnt_kernel<<<gbE, 256, 0, s2>>>(ei);
    scan1_kernel<<<SCB, 256, 0, s2>>>();
    scan2_kernel<<<1, 256, 0, s2>>>();
    scan3_kernel<<<SCB, 256, 0, s2>>>();
    fill_kernel<<<gbE, 256, 0, s2>>>(ei);
    cudaEventRecord(eJoin, s2);

    // ---- branch B (stream 0): gemm0 + gemm1 (no CSR dependence) ----
    k0<<<gbG, 256, sm0>>>(x, W0, pt, nullptr, nullptr, nullptr, 1.f, s0m, s0q);
    k12<<<gbG, 256, sm1>>>(pt, W1, pt2, pt, s0m, s0q, 0.5f, nullptr, nullptr);

    // ---- join: gather1 needs CSR + selfw ----
    cudaStreamWaitEvent(0, eJoin, 0);
    gather_kernel<HID, 1><<<gbW, 512>>>(pt2, pu, pt, s0m, s0q, s1m, s1q);

    // ---- layer 2 (beta = 0.25) ----
    k12<<<gbG, 256, sm1>>>(pu, W2, pt2, pu, s1m, s1q, 0.25f, nullptr, nullptr);
    gather_kernel<HID, 1><<<gbW, 512>>>(pt2, pu, pt, s0m, s0q, s2m, s2q);

    // ---- final: c = bn2relu(u) @ W3^T ; out = spmm(c) ----
    k3<<<gbG, 256, sm3>>>(pu, W3, pc, nullptr, s2m, s2q, 1.f, nullptr, nullptr);
    gather_kernel<OUTC, 0><<<gbW, 512>>>(pc, out, nullptr, nullptr, nullptr, nullptr, nullptr);
}

// round 14
// speedup vs baseline: 1.8678x; 1.1014x over previous
#include <cuda_runtime.h>
#include <cuda_bf16.h>
#include <cstdint>

#define NN 50000
#define NE 800000
#define INC 128
#define HID 96
#define OUTC 40
#define SCB 196   // scan blocks: 196*256 = 50176 >= NN

__device__ float g_dinv[NN];
__device__ float g_selfw[NN];
__device__ int   g_cnt[NN];
__device__ int   g_fill[NN];
__device__ int   g_rowptr[NN + 1];
__device__ int   g_bsum[256];
__device__ int   g_boff[256];
__device__ int   g_col[NE];
__device__ float g_ew[NE];
__device__ float g_t [NN * HID];
__device__ float g_t2[NN * HID];
__device__ float g_u [NN * HID];
__device__ float g_c [NN * OUTC];
__device__ float g_sum[3 * HID];
__device__ float g_sq [3 * HID];

// ---------------------------------------------------------------------------
// helpers
// ---------------------------------------------------------------------------
__device__ __forceinline__ void bn_params(float sum, float sq, float& m, float& s) {
    const float invN = 1.f / (float)NN;
    m = sum * invN;
    float v = sq * invN - m * m;
    s = rsqrtf(v + 1e-5f);
}

// pack two bf16 (x -> low, y -> high)
__device__ __forceinline__ uint32_t pk(__nv_bfloat16 x, __nv_bfloat16 y) {
    __nv_bfloat162 h2;
    h2.x = x; h2.y = y;
    return *(uint32_t*)&h2;
}
// split (x,y) into hi/lo bf16 pairs
__device__ __forceinline__ void split2(float x, float y, uint32_t& hi, uint32_t& lo) {
    __nv_bfloat16 hx = __float2bfloat16_rn(x);
    __nv_bfloat16 hy = __float2bfloat16_rn(y);
    float rx = x - __bfloat162float(hx);
    float ry = y - __bfloat162float(hy);
    hi = pk(hx, hy);
    lo = pk(__float2bfloat16_rn(rx), __float2bfloat16_rn(ry));
}

__device__ __forceinline__ void mma_bf16(float& c0, float& c1, float& c2, float& c3,
                                         uint32_t a0, uint32_t a1, uint32_t a2, uint32_t a3,
                                         uint32_t b0, uint32_t b1) {
    asm volatile(
        "mma.sync.aligned.m16n8k16.row.col.f32.bf16.bf16.f32 "
        "{%0,%1,%2,%3}, {%4,%5,%6,%7}, {%8,%9}, {%0,%1,%2,%3};"
        : "+f"(c0), "+f"(c1), "+f"(c2), "+f"(c3)
        : "r"(a0), "r"(a1), "r"(a2), "r"(a3), "r"(b0), "r"(b1));
}

// ---------------------------------------------------------------------------
// Prep kernels (unchanged R11)
// ---------------------------------------------------------------------------
__global__ void zero_prep_kernel() {
    int i = blockIdx.x * blockDim.x + threadIdx.x;
    if (i < NN) { g_cnt[i] = 0; g_fill[i] = 0; }
    if (i < 3 * HID) { g_sum[i] = 0.f; g_sq[i] = 0.f; }
}

__global__ void cnt_kernel(const int* __restrict__ ei) {
    int e = blockIdx.x * blockDim.x + threadIdx.x;
    if (e >= NE) return;
    int s = ei[e];
    int d = ei[NE + e];
    if (s != d) atomicAdd(&g_cnt[d], 1);
}

__global__ void scan1_kernel() {
    __shared__ int sh[256];
    int i = blockIdx.x * 256 + threadIdx.x;
    sh[threadIdx.x] = (i < NN) ? g_cnt[i] : 0;
    __syncthreads();
    for (int o = 128; o > 0; o >>= 1) {
        if (threadIdx.x < o) sh[threadIdx.x] += sh[threadIdx.x + o];
        __syncthreads();
    }
    if (threadIdx.x == 0) g_bsum[blockIdx.x] = sh[0];
}

__global__ void scan2_kernel() {
    __shared__ int sh[256];
    int t = threadIdx.x;
    int v = (t < SCB) ? g_bsum[t] : 0;
    sh[t] = v;
    __syncthreads();
    for (int o = 1; o < 256; o <<= 1) {
        int add = (t >= o) ? sh[t - o] : 0;
        __syncthreads();
        sh[t] += add;
        __syncthreads();
    }
    if (t < SCB) g_boff[t] = sh[t] - v;
    if (t == 255) g_rowptr[NN] = sh[255];
}

__global__ void scan3_kernel() {
    __shared__ int sh[256];
    int t = threadIdx.x;
    int i = blockIdx.x * 256 + t;
    int v = (i < NN) ? g_cnt[i] : 0;
    sh[t] = v;
    __syncthreads();
    for (int o = 1; o < 256; o <<= 1) {
        int add = (t >= o) ? sh[t - o] : 0;
        __syncthreads();
        sh[t] += add;
        __syncthreads();
    }
    if (i < NN) {
        g_rowptr[i] = g_boff[blockIdx.x] + sh[t] - v;
        float d = (float)v + 1.f;
        g_dinv[i]  = rsqrtf(d);
        g_selfw[i] = 1.f / d;
    }
}

__global__ void fill_kernel(const int* __restrict__ ei) {
    int e = blockIdx.x * blockDim.x + threadIdx.x;
    if (e >= NE) return;
    int s = ei[e];
    int d = ei[NE + e];
    if (s == d) return;
    int pos = g_rowptr[d] + atomicAdd(&g_fill[d], 1);
    g_col[pos] = s;
    g_ew[pos] = g_dinv[s] * g_dinv[d];
}

// ---------------------------------------------------------------------------
// bf16 3-term mma.sync GEMM: Out[256-tile, NOUT] = normA(A) @ W^T
// A split hi/lo bf16, W split hi/lo; acc = Ahi*Bhi + Ahi*Blo + Alo*Bhi (fp32).
// 512 threads = 16 warps; warp w computes rows [w*16, w*16+16).
// NORM=1: relu((a-mean)*scl) at staging (params from raw sums in sIn/qIn).
// BLEND=1: Out = beta*acc + (1-beta)*normA(blendSrc)  (NOUT == K).
// STATS=1: fused column sums/sumsq of written Out.
// ---------------------------------------------------------------------------
template <int K, int NOUT, int NORM, int STATS, int BLEND>
__global__ void __launch_bounds__(512)
gemm_mma(const float* __restrict__ A, const float* __restrict__ Wg,
         float* __restrict__ Out, const float* __restrict__ blendSrc,
         const float* __restrict__ sIn, const float* __restrict__ qIn,
         float beta, float* __restrict__ sOut, float* __restrict__ qOut) {
    constexpr int RSA = (K == 128) ? 136 : 104;   // padded row stride in bf16
    constexpr int RS2 = RSA / 2;                  // in u32 (bf16 pairs)
    constexpr int NT = NOUT / 8;                  // n-tiles
    constexpr int NK = K / 16;                    // k-steps

    extern __shared__ char smraw[];
    uint32_t* Ahi = (uint32_t*)smraw;             // 256*RS2
    uint32_t* Alo = Ahi + 256 * RS2;
    uint32_t* Bhi = Alo + 256 * RS2;              // NOUT*RS2
    uint32_t* Blo = Bhi + NOUT * RS2;
    float* bnM = (float*)(Blo + NOUT * RS2);      // K (NORM)
    float* bnS = bnM + (NORM ? K : 0);
    float* cS  = bnS + (NORM ? K : 0);            // NOUT (STATS)
    float* cQ  = cS + (STATS ? NOUT : 0);

    int tid = threadIdx.x;
    int rowbase = blockIdx.x * 256;

    if (NORM && tid < K) {
        float m, s;
        bn_params(sIn[tid], qIn[tid], m, s);
        bnM[tid] = m;
        bnS[tid] = s;
    }
    if (STATS && tid < NOUT) { cS[tid] = 0.f; cQ[tid] = 0.f; }
    __syncthreads();   // bnM/bnS (and cS/cQ) visible before staging reads them

    // ---- stage A (256 x K), split hi/lo ----
    for (int i = tid; i < 256 * (K / 4); i += 512) {
        int r = i / (K / 4), c4 = i % (K / 4);
        int row = rowbase + r;
        float4 v = (row < NN) ? __ldg((const float4*)&A[(size_t)row * K + c4 * 4])
                              : make_float4(0.f, 0.f, 0.f, 0.f);
        if (NORM) {
            int c = c4 * 4;
            v.x = fmaxf((v.x - bnM[c + 0]) * bnS[c + 0], 0.f);
            v.y = fmaxf((v.y - bnM[c + 1]) * bnS[c + 1], 0.f);
            v.z = fmaxf((v.z - bnM[c + 2]) * bnS[c + 2], 0.f);
            v.w = fmaxf((v.w - bnM[c + 3]) * bnS[c + 3], 0.f);
        }
        uint32_t h0, l0, h1, l1;
        split2(v.x, v.y, h0, l0);
        split2(v.z, v.w, h1, l1);
        int idx = r * RS2 + c4 * 2;
        Ahi[idx] = h0; Ahi[idx + 1] = h1;
        Alo[idx] = l0; Alo[idx + 1] = l1;
    }
    // ---- stage B = W (NOUT x K), split hi/lo ----
    for (int i = tid; i < NOUT * (K / 4); i += 512) {
        int n = i / (K / 4), c4 = i % (K / 4);
        float4 v = __ldg((const float4*)&Wg[(size_t)n * K + c4 * 4]);
        uint32_t h0, l0, h1, l1;
        split2(v.x, v.y, h0, l0);
        split2(v.z, v.w, h1, l1);
        int idx = n * RS2 + c4 * 2;
        Bhi[idx] = h0; Bhi[idx + 1] = h1;
        Blo[idx] = l0; Blo[idx + 1] = l1;
    }
    __syncthreads();

    // ---- mainloop ----
    int w = tid >> 5, lane = tid & 31;
    int g = lane >> 2, t = lane & 3;
    int wrow = w * 16;
    int aoff0 = (wrow + g) * RS2;
    int aoff1 = (wrow + g + 8) * RS2;

    float acc[NT][4];
#pragma unroll
    for (int nt = 0; nt < NT; nt++)
#pragma unroll
        for (int j = 0; j < 4; j++) acc[nt][j] = 0.f;

#pragma unroll
    for (int pass = 0; pass < 3; pass++) {
        const uint32_t* Aa = (pass == 2) ? Alo : Ahi;
        const uint32_t* Bb = (pass == 1) ? Blo : Bhi;
#pragma unroll
        for (int ks = 0; ks < NK; ks++) {
            uint32_t a0 = Aa[aoff0 + ks * 8 + t];
            uint32_t a1 = Aa[aoff1 + ks * 8 + t];
            uint32_t a2 = Aa[aoff0 + ks * 8 + 4 + t];
            uint32_t a3 = Aa[aoff1 + ks * 8 + 4 + t];
#pragma unroll
            for (int nt = 0; nt < NT; nt++) {
                uint32_t b0 = Bb[(nt * 8 + g) * RS2 + ks * 8 + t];
                uint32_t b1 = Bb[(nt * 8 + g) * RS2 + ks * 8 + 4 + t];
                mma_bf16(acc[nt][0], acc[nt][1], acc[nt][2], acc[nt][3],
                         a0, a1, a2, a3, b0, b1);
            }
        }
    }

    // ---- epilogue ----
    int r0 = rowbase + wrow + g;
    int r1 = r0 + 8;
    bool v0 = r0 < NN, v1 = r1 < NN;

#pragma unroll
    for (int nt = 0; nt < NT; nt++) {
        int c = nt * 8 + 2 * t;
        float d0 = acc[nt][0], d1 = acc[nt][1];
        float d2 = acc[nt][2], d3 = acc[nt][3];
        if (BLEND) {
            float2 b0 = v0 ? *(const float2*)&blendSrc[(size_t)r0 * NOUT + c]
                           : make_float2(0.f, 0.f);
            float2 b1 = v1 ? *(const float2*)&blendSrc[(size_t)r1 * NOUT + c]
                           : make_float2(0.f, 0.f);
            float m0 = bnM[c], m1 = bnM[c + 1], s0 = bnS[c], s1 = bnS[c + 1];
            d0 = beta * d0 + (1.f - beta) * fmaxf((b0.x - m0) * s0, 0.f);
            d1 = beta * d1 + (1.f - beta) * fmaxf((b0.y - m1) * s1, 0.f);
            d2 = beta * d2 + (1.f - beta) * fmaxf((b1.x - m0) * s0, 0.f);
            d3 = beta * d3 + (1.f - beta) * fmaxf((b1.y - m1) * s1, 0.f);
        }
        if (v0) *(float2*)&Out[(size_t)r0 * NOUT + c] = make_float2(d0, d1);
        if (v1) *(float2*)&Out[(size_t)r1 * NOUT + c] = make_float2(d2, d3);
        if (STATS) {
            float e0 = v0 ? d0 : 0.f, e1 = v0 ? d1 : 0.f;
            float e2 = v1 ? d2 : 0.f, e3 = v1 ? d3 : 0.f;
            float sa = e0 + e2, sb = e1 + e3;
            float qa = e0 * e0 + e2 * e2, qb = e1 * e1 + e3 * e3;
#pragma unroll
            for (int o = 4; o < 32; o <<= 1) {
                sa += __shfl_xor_sync(0xFFFFFFFFu, sa, o);
                sb += __shfl_xor_sync(0xFFFFFFFFu, sb, o);
                qa += __shfl_xor_sync(0xFFFFFFFFu, qa, o);
                qb += __shfl_xor_sync(0xFFFFFFFFu, qb, o);
            }
            if (lane < 4) {
                atomicAdd(&cS[c], sa);
                atomicAdd(&cS[c + 1], sb);
                atomicAdd(&cQ[c], qa);
                atomicAdd(&cQ[c + 1], qb);
            }
        }
    }

    if (STATS) {
        __syncthreads();
        if (tid < NOUT) {
            atomicAdd(&sOut[tid], cS[tid]);
            atomicAdd(&qOut[tid], cQ[tid]);
        }
    }
}

// ---------------------------------------------------------------------------
// CSR gather SpMM (unchanged R11 winner)
// ---------------------------------------------------------------------------
template <int F, int MODE>
__global__ void gather_kernel(const float* __restrict__ X, float* __restrict__ Y,
                              const float* __restrict__ h0raw,
                              const float* __restrict__ sums0,
                              const float* __restrict__ sq0,
                              float* __restrict__ sumsOut,
                              float* __restrict__ sqOut) {
    constexpr int NV = F / 4;
    __shared__ __align__(16) float ssum[HID];
    __shared__ __align__(16) float ssq[HID];
    __shared__ __align__(16) float sm_m[HID];
    __shared__ __align__(16) float sm_s[HID];
    int tid = threadIdx.x;
    if (MODE == 1) {
        if (tid < F) {
            ssum[tid] = 0.f;
            ssq[tid] = 0.f;
            float m, s;
            bn_params(sums0[tid], sq0[tid], m, s);
            sm_m[tid] = m;
            sm_s[tid] = s;
        }
        __syncthreads();
    }
    int node = blockIdx.x * (blockDim.x >> 5) + (tid >> 5);
    int lane = tid & 31;
    bool act = lane < NV;
    const float4* Xv = (const float4*)X;

    float4 sum = make_float4(0.f, 0.f, 0.f, 0.f);
    int p   = g_rowptr[node];
    int end = g_rowptr[node + 1];

    for (; p + 4 <= end; p += 4) {
        int   c0 = __ldg(&g_col[p]),     c1 = __ldg(&g_col[p + 1]);
        int   c2 = __ldg(&g_col[p + 2]), c3 = __ldg(&g_col[p + 3]);
        float w0 = __ldg(&g_ew[p]),      w1 = __ldg(&g_ew[p + 1]);
        float w2 = __ldg(&g_ew[p + 2]),  w3 = __ldg(&g_ew[p + 3]);
        if (act) {
            float4 v0 = __ldg(&Xv[(size_t)c0 * NV + lane]);
            float4 v1 = __ldg(&Xv[(size_t)c1 * NV + lane]);
            float4 v2 = __ldg(&Xv[(size_t)c2 * NV + lane]);
            float4 v3 = __ldg(&Xv[(size_t)c3 * NV + lane]);
            sum.x += w0 * v0.x + w1 * v1.x + w2 * v2.x + w3 * v3.x;
            sum.y += w0 * v0.y + w1 * v1.y + w2 * v2.y + w3 * v3.y;
            sum.z += w0 * v0.z + w1 * v1.z + w2 * v2.z + w3 * v3.z;
            sum.w += w0 * v0.w + w1 * v1.w + w2 * v2.w + w3 * v3.w;
        }
    }
    for (; p < end; p++) {
        int c = __ldg(&g_col[p]);
        float w = __ldg(&g_ew[p]);
        if (act) {
            float4 v = __ldg(&Xv[(size_t)c * NV + lane]);
            sum.x += w * v.x; sum.y += w * v.y;
            sum.z += w * v.z; sum.w += w * v.w;
        }
    }

    if (act) {
        float sw = g_selfw[node];
        float4 xv = __ldg(&Xv[(size_t)node * NV + lane]);
        float4 v;
        v.x = sum.x + sw * xv.x;
        v.y = sum.y + sw * xv.y;
        v.z = sum.z + sw * xv.z;
        v.w = sum.w + sw * xv.w;
        if (MODE == 1) {
            float4 m  = ((const float4*)sm_m)[lane];
            float4 s  = ((const float4*)sm_s)[lane];
            float4 hr = __ldg(&((const float4*)h0raw)[(size_t)node * NV + lane]);
            v.x = 0.9f * v.x + 0.1f * fmaxf((hr.x - m.x) * s.x, 0.f);
            v.y = 0.9f * v.y + 0.1f * fmaxf((hr.y - m.y) * s.y, 0.f);
            v.z = 0.9f * v.z + 0.1f * fmaxf((hr.z - m.z) * s.z, 0.f);
            v.w = 0.9f * v.w + 0.1f * fmaxf((hr.w - m.w) * s.w, 0.f);
        }
        ((float4*)Y)[(size_t)node * NV + lane] = v;
        if (MODE == 1) {
            int col = lane * 4;
            atomicAdd(&ssum[col + 0], v.x);
            atomicAdd(&ssum[col + 1], v.y);
            atomicAdd(&ssum[col + 2], v.z);
            atomicAdd(&ssum[col + 3], v.w);
            atomicAdd(&ssq[col + 0], v.x * v.x);
            atomicAdd(&ssq[col + 1], v.y * v.y);
            atomicAdd(&ssq[col + 2], v.z * v.z);
            atomicAdd(&ssq[col + 3], v.w * v.w);
        }
    }

    if (MODE == 1) {
        __syncthreads();
        if (tid < F) {
            atomicAdd(&sumsOut[tid], ssum[tid]);
            atomicAdd(&sqOut[tid], ssq[tid]);
        }
    }
}

// ---------------------------------------------------------------------------
extern "C" void kernel_launch(void* const* d_in, const int* in_sizes, int n_in,
                              void* d_out, int out_size) {
    const float* x  = (const float*)d_in[0];
    const int*   ei = (const int*)d_in[1];
    const float* W0 = (const float*)d_in[2];
    const float* W1 = (const float*)d_in[3];
    const float* W2 = (const float*)d_in[4];
    const float* W3 = (const float*)d_in[5];
    float* out = (float*)d_out;

    float *pt, *pt2, *pu, *pc, *psum, *psq;
    cudaGetSymbolAddress((void**)&pt, g_t);
    cudaGetSymbolAddress((void**)&pt2, g_t2);
    cudaGetSymbolAddress((void**)&pu, g_u);
    cudaGetSymbolAddress((void**)&pc, g_c);
    cudaGetSymbolAddress((void**)&psum, g_sum);
    cudaGetSymbolAddress((void**)&psq, g_sq);

    const int gbE = (NE + 255) / 256;
    const int gbN = (NN + 255) / 256;
    const int gbG = (NN + 255) / 256;   // 196 tiles of 256 rows
    const int gbW = NN / 16;

    float* s0m = psum + 0 * HID; float* s0q = psq + 0 * HID;
    float* s1m = psum + 1 * HID; float* s1q = psq + 1 * HID;
    float* s2m = psum + 2 * HID; float* s2q = psq + 2 * HID;

    // dynamic smem: A hi/lo + B hi/lo (+ bn, stats)
    const int sm0 = 256 * 68 * 4 * 2 + 96 * 68 * 4 * 2 + 96 * 8;          // 192,256
    const int sm1 = 256 * 52 * 4 * 2 + 96 * 52 * 4 * 2 + 96 * 8;          // 147,200
    const int sm3 = 256 * 52 * 4 * 2 + 40 * 52 * 4 * 2 + 96 * 8;          // 123,904

    auto k0  = gemm_mma<INC, HID, 0, 1, 0>;
    auto k12 = gemm_mma<HID, HID, 1, 0, 1>;
    auto k3  = gemm_mma<HID, OUTC, 1, 0, 0>;
    cudaFuncSetAttribute(k0, cudaFuncAttributeMaxDynamicSharedMemorySize, sm0);
    cudaFuncSetAttribute(k12, cudaFuncAttributeMaxDynamicSharedMemorySize, sm1);
    cudaFuncSetAttribute(k3, cudaFuncAttributeMaxDynamicSharedMemorySize, sm3);

    // Side stream + events for capture-safe fork/join (leaked by design;
    // kernel_launch runs only ~2x).
    cudaStream_t s2;
    cudaStreamCreateWithFlags(&s2, cudaStreamNonBlocking);
    cudaEvent_t eFork, eJoin;
    cudaEventCreateWithFlags(&eFork, cudaEventDisableTiming);
    cudaEventCreateWithFlags(&eJoin, cudaEventDisableTiming);

    // ---- zero (both branches depend on it) ----
    zero_prep_kernel<<<gbN, 256>>>();
    cudaEventRecord(eFork, 0);
    cudaStreamWaitEvent(s2, eFork, 0);

    // ---- branch A (stream s2): CSR build ----
    cnt_kernel<<<gbE, 256, 0, s2>>>(ei);
    scan1_kernel<<<SCB, 256, 0, s2>>>();
    scan2_kernel<<<1, 256, 0, s2>>>();
    scan3_kernel<<<SCB, 256, 0, s2>>>();
    fill_kernel<<<gbE, 256, 0, s2>>>(ei);
    cudaEventRecord(eJoin, s2);

    // ---- branch B (stream 0): gemm0 + gemm1 ----
    k0<<<gbG, 512, sm0>>>(x, W0, pt, nullptr, nullptr, nullptr, 1.f, s0m, s0q);
    k12<<<gbG, 512, sm1>>>(pt, W1, pt2, pt, s0m, s0q, 0.5f, nullptr, nullptr);

    // ---- join: gather1 needs CSR + selfw ----
    cudaStreamWaitEvent(0, eJoin, 0);
    gather_kernel<HID, 1><<<gbW, 512>>>(pt2, pu, pt, s0m, s0q, s1m, s1q);

    // ---- layer 2 (beta = 0.25) ----
    k12<<<gbG, 512, sm1>>>(pu, W2, pt2, pu, s1m, s1q, 0.25f, nullptr, nullptr);
    gather_kernel<HID, 1><<<gbW, 512>>>(pt2, pu, pt, s0m, s0q, s2m, s2q);

    // ---- final: c = bn2relu(u) @ W3^T ; out = spmm(c) ----
    k3<<<gbG, 512, sm3>>>(pu, W3, pc, nullptr, s2m, s2q, 1.f, nullptr, nullptr);
    gather_kernel<OUTC, 0><<<gbW, 512>>>(pc, out, nullptr, nullptr, nullptr, nullptr, nullptr);
}

// round 15
// speedup vs baseline: 1.9181x; 1.0269x over previous
#include <cuda_runtime.h>
#include <cuda_bf16.h>
#include <cstdint>

#define NN 50000
#define NE 800000
#define INC 128
#define HID 96
#define OUTC 40
#define SCB 196   // scan blocks: 196*256 = 50176 >= NN

__device__ float g_dinv[NN];
__device__ float g_selfw[NN];
__device__ int   g_cnt[NN];
__device__ int   g_fill[NN];
__device__ int   g_rowptr[NN + 1];
__device__ int   g_bsum[256];
__device__ int   g_boff[256];
__device__ int   g_col[NE];
__device__ float g_ew[NE];
__device__ float g_t [NN * HID];
__device__ float g_t2[NN * HID];
__device__ float g_u [NN * HID];
__device__ float g_c [NN * OUTC];
__device__ float g_sum[3 * HID];
__device__ float g_sq [3 * HID];

// ---------------------------------------------------------------------------
// helpers
// ---------------------------------------------------------------------------
__device__ __forceinline__ void bn_params(float sum, float sq, float& m, float& s) {
    const float invN = 1.f / (float)NN;
    m = sum * invN;
    float v = sq * invN - m * m;
    s = rsqrtf(v + 1e-5f);
}

__device__ __forceinline__ uint32_t pk(__nv_bfloat16 x, __nv_bfloat16 y) {
    __nv_bfloat162 h2;
    h2.x = x; h2.y = y;
    return *(uint32_t*)&h2;
}
__device__ __forceinline__ void split2(float x, float y, uint32_t& hi, uint32_t& lo) {
    __nv_bfloat16 hx = __float2bfloat16_rn(x);
    __nv_bfloat16 hy = __float2bfloat16_rn(y);
    float rx = x - __bfloat162float(hx);
    float ry = y - __bfloat162float(hy);
    hi = pk(hx, hy);
    lo = pk(__float2bfloat16_rn(rx), __float2bfloat16_rn(ry));
}

__device__ __forceinline__ void mma_bf16(float& c0, float& c1, float& c2, float& c3,
                                         uint32_t a0, uint32_t a1, uint32_t a2, uint32_t a3,
                                         uint32_t b0, uint32_t b1) {
    asm volatile(
        "mma.sync.aligned.m16n8k16.row.col.f32.bf16.bf16.f32 "
        "{%0,%1,%2,%3}, {%4,%5,%6,%7}, {%8,%9}, {%0,%1,%2,%3};"
        : "+f"(c0), "+f"(c1), "+f"(c2), "+f"(c3)
        : "r"(a0), "r"(a1), "r"(a2), "r"(a3), "r"(b0), "r"(b1));
}

// ---------------------------------------------------------------------------
// Prep kernels
// ---------------------------------------------------------------------------
__global__ void zero_prep_kernel() {
    int i = blockIdx.x * blockDim.x + threadIdx.x;
    if (i < NN) { g_cnt[i] = 0; g_fill[i] = 0; }
    if (i < 3 * HID) { g_sum[i] = 0.f; g_sq[i] = 0.f; }
}

__global__ void cnt_kernel(const int* __restrict__ ei) {
    int e = blockIdx.x * blockDim.x + threadIdx.x;
    if (e >= NE) return;
    int s = ei[e];
    int d = ei[NE + e];
    if (s != d) atomicAdd(&g_cnt[d], 1);
}

__global__ void scan1_kernel() {
    __shared__ int sh[256];
    int i = blockIdx.x * 256 + threadIdx.x;
    sh[threadIdx.x] = (i < NN) ? g_cnt[i] : 0;
    __syncthreads();
    for (int o = 128; o > 0; o >>= 1) {
        if (threadIdx.x < o) sh[threadIdx.x] += sh[threadIdx.x + o];
        __syncthreads();
    }
    if (threadIdx.x == 0) g_bsum[blockIdx.x] = sh[0];
}

__global__ void scan2_kernel() {
    __shared__ int sh[256];
    int t = threadIdx.x;
    int v = (t < SCB) ? g_bsum[t] : 0;
    sh[t] = v;
    __syncthreads();
    for (int o = 1; o < 256; o <<= 1) {
        int add = (t >= o) ? sh[t - o] : 0;
        __syncthreads();
        sh[t] += add;
        __syncthreads();
    }
    if (t < SCB) g_boff[t] = sh[t] - v;
    if (t == 255) g_rowptr[NN] = sh[255];
}

__global__ void scan3_kernel() {
    __shared__ int sh[256];
    int t = threadIdx.x;
    int i = blockIdx.x * 256 + t;
    int v = (i < NN) ? g_cnt[i] : 0;
    sh[t] = v;
    __syncthreads();
    for (int o = 1; o < 256; o <<= 1) {
        int add = (t >= o) ? sh[t - o] : 0;
        __syncthreads();
        sh[t] += add;
        __syncthreads();
    }
    if (i < NN) {
        g_rowptr[i] = g_boff[blockIdx.x] + sh[t] - v;
        float d = (float)v + 1.f;
        g_dinv[i]  = rsqrtf(d);
        g_selfw[i] = 1.f / d;
    }
}

__global__ void fill_kernel(const int* __restrict__ ei) {
    int e = blockIdx.x * blockDim.x + threadIdx.x;
    if (e >= NE) return;
    int s = ei[e];
    int d = ei[NE + e];
    if (s == d) return;
    int pos = g_rowptr[d] + atomicAdd(&g_fill[d], 1);
    g_col[pos] = s;
    g_ew[pos] = g_dinv[s] * g_dinv[d];
}

// ---------------------------------------------------------------------------
// bf16 3-term mma.sync GEMM, TILE rows per block, NTH = (TILE/16)*32 threads.
// acc = Ahi*Bhi + Ahi*Blo + Alo*Bhi (fp32 accum). Warp w: rows [w*16, w*16+16).
// ---------------------------------------------------------------------------
template <int K, int NOUT, int TILE, int NTH, int NORM, int STATS, int BLEND>
__global__ void __launch_bounds__(NTH)
gemm_mma(const float* __restrict__ A, const float* __restrict__ Wg,
         float* __restrict__ Out, const float* __restrict__ blendSrc,
         const float* __restrict__ sIn, const float* __restrict__ qIn,
         float beta, float* __restrict__ sOut, float* __restrict__ qOut) {
    constexpr int RSA = (K == 128) ? 136 : 104;   // padded row stride in bf16
    constexpr int RS2 = RSA / 2;                  // in u32 (bf16 pairs)
    constexpr int NT = NOUT / 8;                  // n-tiles
    constexpr int NK = K / 16;                    // k-steps

    extern __shared__ char smraw[];
    uint32_t* Ahi = (uint32_t*)smraw;             // TILE*RS2
    uint32_t* Alo = Ahi + TILE * RS2;
    uint32_t* Bhi = Alo + TILE * RS2;             // NOUT*RS2
    uint32_t* Blo = Bhi + NOUT * RS2;
    float* bnM = (float*)(Blo + NOUT * RS2);      // K (NORM)
    float* bnS = bnM + (NORM ? K : 0);
    float* cS  = bnS + (NORM ? K : 0);            // NOUT (STATS)
    float* cQ  = cS + (STATS ? NOUT : 0);

    int tid = threadIdx.x;
    int rowbase = blockIdx.x * TILE;

    if (NORM && tid < K) {
        float m, s;
        bn_params(sIn[tid], qIn[tid], m, s);
        bnM[tid] = m;
        bnS[tid] = s;
    }
    if (STATS && tid < NOUT) { cS[tid] = 0.f; cQ[tid] = 0.f; }
    __syncthreads();   // bn/stats SMEM visible before staging

    // ---- stage A (TILE x K), split hi/lo ----
    for (int i = tid; i < TILE * (K / 4); i += NTH) {
        int r = i / (K / 4), c4 = i % (K / 4);
        int row = rowbase + r;
        float4 v = (row < NN) ? __ldg((const float4*)&A[(size_t)row * K + c4 * 4])
                              : make_float4(0.f, 0.f, 0.f, 0.f);
        if (NORM) {
            int c = c4 * 4;
            v.x = fmaxf((v.x - bnM[c + 0]) * bnS[c + 0], 0.f);
            v.y = fmaxf((v.y - bnM[c + 1]) * bnS[c + 1], 0.f);
            v.z = fmaxf((v.z - bnM[c + 2]) * bnS[c + 2], 0.f);
            v.w = fmaxf((v.w - bnM[c + 3]) * bnS[c + 3], 0.f);
        }
        uint32_t h0, l0, h1, l1;
        split2(v.x, v.y, h0, l0);
        split2(v.z, v.w, h1, l1);
        int idx = r * RS2 + c4 * 2;
        Ahi[idx] = h0; Ahi[idx + 1] = h1;
        Alo[idx] = l0; Alo[idx + 1] = l1;
    }
    // ---- stage B = W (NOUT x K), split hi/lo ----
    for (int i = tid; i < NOUT * (K / 4); i += NTH) {
        int n = i / (K / 4), c4 = i % (K / 4);
        float4 v = __ldg((const float4*)&Wg[(size_t)n * K + c4 * 4]);
        uint32_t h0, l0, h1, l1;
        split2(v.x, v.y, h0, l0);
        split2(v.z, v.w, h1, l1);
        int idx = n * RS2 + c4 * 2;
        Bhi[idx] = h0; Bhi[idx + 1] = h1;
        Blo[idx] = l0; Blo[idx + 1] = l1;
    }
    __syncthreads();

    // ---- mainloop ----
    int w = tid >> 5, lane = tid & 31;
    int g = lane >> 2, t = lane & 3;
    int wrow = w * 16;
    int aoff0 = (wrow + g) * RS2;
    int aoff1 = (wrow + g + 8) * RS2;

    float acc[NT][4];
#pragma unroll
    for (int nt = 0; nt < NT; nt++)
#pragma unroll
        for (int j = 0; j < 4; j++) acc[nt][j] = 0.f;

#pragma unroll
    for (int pass = 0; pass < 3; pass++) {
        const uint32_t* Aa = (pass == 2) ? Alo : Ahi;
        const uint32_t* Bb = (pass == 1) ? Blo : Bhi;
#pragma unroll
        for (int ks = 0; ks < NK; ks++) {
            uint32_t a0 = Aa[aoff0 + ks * 8 + t];
            uint32_t a1 = Aa[aoff1 + ks * 8 + t];
            uint32_t a2 = Aa[aoff0 + ks * 8 + 4 + t];
            uint32_t a3 = Aa[aoff1 + ks * 8 + 4 + t];
#pragma unroll
            for (int nt = 0; nt < NT; nt++) {
                uint32_t b0 = Bb[(nt * 8 + g) * RS2 + ks * 8 + t];
                uint32_t b1 = Bb[(nt * 8 + g) * RS2 + ks * 8 + 4 + t];
                mma_bf16(acc[nt][0], acc[nt][1], acc[nt][2], acc[nt][3],
                         a0, a1, a2, a3, b0, b1);
            }
        }
    }

    // ---- epilogue ----
    int r0 = rowbase + wrow + g;
    int r1 = r0 + 8;
    bool v0 = r0 < NN, v1 = r1 < NN;

#pragma unroll
    for (int nt = 0; nt < NT; nt++) {
        int c = nt * 8 + 2 * t;
        float d0 = acc[nt][0], d1 = acc[nt][1];
        float d2 = acc[nt][2], d3 = acc[nt][3];
        if (BLEND) {
            float2 b0 = v0 ? *(const float2*)&blendSrc[(size_t)r0 * NOUT + c]
                           : make_float2(0.f, 0.f);
            float2 b1 = v1 ? *(const float2*)&blendSrc[(size_t)r1 * NOUT + c]
                           : make_float2(0.f, 0.f);
            float m0 = bnM[c], m1 = bnM[c + 1], s0 = bnS[c], s1 = bnS[c + 1];
            d0 = beta * d0 + (1.f - beta) * fmaxf((b0.x - m0) * s0, 0.f);
            d1 = beta * d1 + (1.f - beta) * fmaxf((b0.y - m1) * s1, 0.f);
            d2 = beta * d2 + (1.f - beta) * fmaxf((b1.x - m0) * s0, 0.f);
            d3 = beta * d3 + (1.f - beta) * fmaxf((b1.y - m1) * s1, 0.f);
        }
        if (v0) *(float2*)&Out[(size_t)r0 * NOUT + c] = make_float2(d0, d1);
        if (v1) *(float2*)&Out[(size_t)r1 * NOUT + c] = make_float2(d2, d3);
        if (STATS) {
            float e0 = v0 ? d0 : 0.f, e1 = v0 ? d1 : 0.f;
            float e2 = v1 ? d2 : 0.f, e3 = v1 ? d3 : 0.f;
            float sa = e0 + e2, sb = e1 + e3;
            float qa = e0 * e0 + e2 * e2, qb = e1 * e1 + e3 * e3;
#pragma unroll
            for (int o = 4; o < 32; o <<= 1) {
                sa += __shfl_xor_sync(0xFFFFFFFFu, sa, o);
                sb += __shfl_xor_sync(0xFFFFFFFFu, sb, o);
                qa += __shfl_xor_sync(0xFFFFFFFFu, qa, o);
                qb += __shfl_xor_sync(0xFFFFFFFFu, qb, o);
            }
            if (lane < 4) {
                atomicAdd(&cS[c], sa);
                atomicAdd(&cS[c + 1], sb);
                atomicAdd(&cQ[c], qa);
                atomicAdd(&cQ[c + 1], qb);
            }
        }
    }

    if (STATS) {
        __syncthreads();
        if (tid < NOUT) {
            atomicAdd(&sOut[tid], cS[tid]);
            atomicAdd(&qOut[tid], cQ[tid]);
        }
    }
}

// ---------------------------------------------------------------------------
// CSR gather SpMM, warp per node (F=96). Unchanged R11 winner.
// ---------------------------------------------------------------------------
template <int F, int MODE>
__global__ void gather_kernel(const float* __restrict__ X, float* __restrict__ Y,
                              const float* __restrict__ h0raw,
                              const float* __restrict__ sums0,
                              const float* __restrict__ sq0,
                              float* __restrict__ sumsOut,
                              float* __restrict__ sqOut) {
    constexpr int NV = F / 4;
    __shared__ __align__(16) float ssum[HID];
    __shared__ __align__(16) float ssq[HID];
    __shared__ __align__(16) float sm_m[HID];
    __shared__ __align__(16) float sm_s[HID];
    int tid = threadIdx.x;
    if (MODE == 1) {
        if (tid < F) {
            ssum[tid] = 0.f;
            ssq[tid] = 0.f;
            float m, s;
            bn_params(sums0[tid], sq0[tid], m, s);
            sm_m[tid] = m;
            sm_s[tid] = s;
        }
        __syncthreads();
    }
    int node = blockIdx.x * (blockDim.x >> 5) + (tid >> 5);
    int lane = tid & 31;
    bool act = lane < NV;
    const float4* Xv = (const float4*)X;

    float4 sum = make_float4(0.f, 0.f, 0.f, 0.f);
    int p   = g_rowptr[node];
    int end = g_rowptr[node + 1];

    for (; p + 4 <= end; p += 4) {
        int   c0 = __ldg(&g_col[p]),     c1 = __ldg(&g_col[p + 1]);
        int   c2 = __ldg(&g_col[p + 2]), c3 = __ldg(&g_col[p + 3]);
        float w0 = __ldg(&g_ew[p]),      w1 = __ldg(&g_ew[p + 1]);
        float w2 = __ldg(&g_ew[p + 2]),  w3 = __ldg(&g_ew[p + 3]);
        if (act) {
            float4 v0 = __ldg(&Xv[(size_t)c0 * NV + lane]);
            float4 v1 = __ldg(&Xv[(size_t)c1 * NV + lane]);
            float4 v2 = __ldg(&Xv[(size_t)c2 * NV + lane]);
            float4 v3 = __ldg(&Xv[(size_t)c3 * NV + lane]);
            sum.x += w0 * v0.x + w1 * v1.x + w2 * v2.x + w3 * v3.x;
            sum.y += w0 * v0.y + w1 * v1.y + w2 * v2.y + w3 * v3.y;
            sum.z += w0 * v0.z + w1 * v1.z + w2 * v2.z + w3 * v3.z;
            sum.w += w0 * v0.w + w1 * v1.w + w2 * v2.w + w3 * v3.w;
        }
    }
    for (; p < end; p++) {
        int c = __ldg(&g_col[p]);
        float w = __ldg(&g_ew[p]);
        if (act) {
            float4 v = __ldg(&Xv[(size_t)c * NV + lane]);
            sum.x += w * v.x; sum.y += w * v.y;
            sum.z += w * v.z; sum.w += w * v.w;
        }
    }

    if (act) {
        float sw = g_selfw[node];
        float4 xv = __ldg(&Xv[(size_t)node * NV + lane]);
        float4 v;
        v.x = sum.x + sw * xv.x;
        v.y = sum.y + sw * xv.y;
        v.z = sum.z + sw * xv.z;
        v.w = sum.w + sw * xv.w;
        if (MODE == 1) {
            float4 m  = ((const float4*)sm_m)[lane];
            float4 s  = ((const float4*)sm_s)[lane];
            float4 hr = __ldg(&((const float4*)h0raw)[(size_t)node * NV + lane]);
            v.x = 0.9f * v.x + 0.1f * fmaxf((hr.x - m.x) * s.x, 0.f);
            v.y = 0.9f * v.y + 0.1f * fmaxf((hr.y - m.y) * s.y, 0.f);
            v.z = 0.9f * v.z + 0.1f * fmaxf((hr.z - m.z) * s.z, 0.f);
            v.w = 0.9f * v.w + 0.1f * fmaxf((hr.w - m.w) * s.w, 0.f);
        }
        ((float4*)Y)[(size_t)node * NV + lane] = v;
        if (MODE == 1) {
            int col = lane * 4;
            atomicAdd(&ssum[col + 0], v.x);
            atomicAdd(&ssum[col + 1], v.y);
            atomicAdd(&ssum[col + 2], v.z);
            atomicAdd(&ssum[col + 3], v.w);
            atomicAdd(&ssq[col + 0], v.x * v.x);
            atomicAdd(&ssq[col + 1], v.y * v.y);
            atomicAdd(&ssq[col + 2], v.z * v.z);
            atomicAdd(&ssq[col + 3], v.w * v.w);
        }
    }

    if (MODE == 1) {
        __syncthreads();
        if (tid < F) {
            atomicAdd(&sumsOut[tid], ssum[tid]);
            atomicAdd(&sqOut[tid], ssq[tid]);
        }
    }
}

// ---------------------------------------------------------------------------
// Final gather (F=40): two nodes per warp (half-warp each, 10 active lanes).
// Y = sum + selfw * X.
// ---------------------------------------------------------------------------
__global__ void gather40_kernel(const float* __restrict__ X, float* __restrict__ Y) {
    constexpr int NV = OUTC / 4;   // 10 float4 per row
    int lane = threadIdx.x & 31;
    int half = lane >> 4;          // 0 or 1
    int sub  = lane & 15;
    int node = (blockIdx.x * (blockDim.x >> 5) + (threadIdx.x >> 5)) * 2 + half;
    if (node >= NN) return;
    bool act = sub < NV;
    const float4* Xv = (const float4*)X;

    float4 sum = make_float4(0.f, 0.f, 0.f, 0.f);
    int p   = g_rowptr[node];
    int end = g_rowptr[node + 1];

    for (; p + 4 <= end; p += 4) {
        int   c0 = __ldg(&g_col[p]),     c1 = __ldg(&g_col[p + 1]);
        int   c2 = __ldg(&g_col[p + 2]), c3 = __ldg(&g_col[p + 3]);
        float w0 = __ldg(&g_ew[p]),      w1 = __ldg(&g_ew[p + 1]);
        float w2 = __ldg(&g_ew[p + 2]),  w3 = __ldg(&g_ew[p + 3]);
        if (act) {
            float4 v0 = __ldg(&Xv[(size_t)c0 * NV + sub]);
            float4 v1 = __ldg(&Xv[(size_t)c1 * NV + sub]);
            float4 v2 = __ldg(&Xv[(size_t)c2 * NV + sub]);
            float4 v3 = __ldg(&Xv[(size_t)c3 * NV + sub]);
            sum.x += w0 * v0.x + w1 * v1.x + w2 * v2.x + w3 * v3.x;
            sum.y += w0 * v0.y + w1 * v1.y + w2 * v2.y + w3 * v3.y;
            sum.z += w0 * v0.z + w1 * v1.z + w2 * v2.z + w3 * v3.z;
            sum.w += w0 * v0.w + w1 * v1.w + w2 * v2.w + w3 * v3.w;
        }
    }
    for (; p < end; p++) {
        int c = __ldg(&g_col[p]);
        float w = __ldg(&g_ew[p]);
        if (act) {
            float4 v = __ldg(&Xv[(size_t)c * NV + sub]);
            sum.x += w * v.x; sum.y += w * v.y;
            sum.z += w * v.z; sum.w += w * v.w;
        }
    }

    if (act) {
        float sw = g_selfw[node];
        float4 xv = __ldg(&Xv[(size_t)node * NV + sub]);
        float4 v;
        v.x = sum.x + sw * xv.x;
        v.y = sum.y + sw * xv.y;
        v.z = sum.z + sw * xv.z;
        v.w = sum.w + sw * xv.w;
        ((float4*)Y)[(size_t)node * NV + sub] = v;
    }
}

// ---------------------------------------------------------------------------
extern "C" void kernel_launch(void* const* d_in, const int* in_sizes, int n_in,
                              void* d_out, int out_size) {
    const float* x  = (const float*)d_in[0];
    const int*   ei = (const int*)d_in[1];
    const float* W0 = (const float*)d_in[2];
    const float* W1 = (const float*)d_in[3];
    const float* W2 = (const float*)d_in[4];
    const float* W3 = (const float*)d_in[5];
    float* out = (float*)d_out;

    float *pt, *pt2, *pu, *pc, *psum, *psq;
    cudaGetSymbolAddress((void**)&pt, g_t);
    cudaGetSymbolAddress((void**)&pt2, g_t2);
    cudaGetSymbolAddress((void**)&pu, g_u);
    cudaGetSymbolAddress((void**)&pc, g_c);
    cudaGetSymbolAddress((void**)&psum, g_sum);
    cudaGetSymbolAddress((void**)&psq, g_sq);

    const int gbE = (NE + 255) / 256;
    const int gbN = (NN + 255) / 256;
    const int gbG0 = (NN + 255) / 256;   // 196 tiles of 256 rows (k0)
    const int gbG1 = (NN + 127) / 128;   // 391 tiles of 128 rows (k12, k3)
    const int gbW = NN / 16;
    const int gbW40 = (NN + 31) / 32;    // 2 nodes per warp

    float* s0m = psum + 0 * HID; float* s0q = psq + 0 * HID;
    float* s1m = psum + 1 * HID; float* s1q = psq + 1 * HID;
    float* s2m = psum + 2 * HID; float* s2q = psq + 2 * HID;

    // dynamic smem
    const int sm0 = 256 * 68 * 8 + 96 * 68 * 8 + 96 * 8;    // 192,256 (1 CTA/SM)
    const int sm1 = 128 * 52 * 8 + 96 * 52 * 8 + 96 * 8 + 96 * 8;  // 94,720 (2 CTA/SM)
    const int sm3 = 128 * 52 * 8 + 40 * 52 * 8 + 96 * 8;    // 70,656 (3 CTA/SM)

    auto k0  = gemm_mma<INC, HID, 256, 512, 0, 1, 0>;
    auto k12 = gemm_mma<HID, HID, 128, 256, 1, 0, 1>;
    auto k3  = gemm_mma<HID, OUTC, 128, 256, 1, 0, 0>;
    cudaFuncSetAttribute(k0, cudaFuncAttributeMaxDynamicSharedMemorySize, sm0);
    cudaFuncSetAttribute(k12, cudaFuncAttributeMaxDynamicSharedMemorySize, sm1);
    cudaFuncSetAttribute(k3, cudaFuncAttributeMaxDynamicSharedMemorySize, sm3);

    // Side stream + events for capture-safe fork/join (leaked by design).
    cudaStream_t s2;
    cudaStreamCreateWithFlags(&s2, cudaStreamNonBlocking);
    cudaEvent_t eFork, eJoin;
    cudaEventCreateWithFlags(&eFork, cudaEventDisableTiming);
    cudaEventCreateWithFlags(&eJoin, cudaEventDisableTiming);

    // ---- zero (both branches depend on it) ----
    zero_prep_kernel<<<gbN, 256>>>();
    cudaEventRecord(eFork, 0);
    cudaStreamWaitEvent(s2, eFork, 0);

    // Submission order puts k0 at index 3 (ncu capture slot).
    cnt_kernel<<<gbE, 256, 0, s2>>>(ei);
    scan1_kernel<<<SCB, 256, 0, s2>>>();
    k0<<<gbG0, 512, sm0>>>(x, W0, pt, nullptr, nullptr, nullptr, 1.f, s0m, s0q);
    scan2_kernel<<<1, 256, 0, s2>>>();
    scan3_kernel<<<SCB, 256, 0, s2>>>();
    fill_kernel<<<gbE, 256, 0, s2>>>(ei);
    cudaEventRecord(eJoin, s2);

    // ---- layer 1 GEMM (stream 0, no CSR dependence) ----
    k12<<<gbG1, 256, sm1>>>(pt, W1, pt2, pt, s0m, s0q, 0.5f, nullptr, nullptr);

    // ---- join: gather1 needs CSR + selfw ----
    cudaStreamWaitEvent(0, eJoin, 0);
    gather_kernel<HID, 1><<<gbW, 512>>>(pt2, pu, pt, s0m, s0q, s1m, s1q);

    // ---- layer 2 (beta = 0.25) ----
    k12<<<gbG1, 256, sm1>>>(pu, W2, pt2, pu, s1m, s1q, 0.25f, nullptr, nullptr);
    gather_kernel<HID, 1><<<gbW, 512>>>(pt2, pu, pt, s0m, s0q, s2m, s2q);

    // ---- final: c = bn2relu(u) @ W3^T ; out = spmm(c) ----
    k3<<<gbG1, 256, sm3>>>(pu, W3, pc, nullptr, s2m, s2q, 1.f, nullptr, nullptr);
    gather40_kernel<<<gbW40, 512>>>(pc, out);
}

// round 16
// speedup vs baseline: 2.0263x; 1.0564x over previous
#include <cuda_runtime.h>
#include <cuda_bf16.h>
#include <cstdint>

#define NN 50000
#define NE 800000
#define INC 128
#define HID 96
#define OUTC 40
#define SCB 196   // scan blocks: 196*256 = 50176 >= NN

__device__ float g_dinv[NN];
__device__ float g_selfw[NN];
__device__ int   g_cnt[NN];
__device__ int   g_fill[NN];
__device__ int   g_rowptr[NN + 1];
__device__ int   g_bsum[256];
__device__ int   g_boff[256];
__device__ int   g_col[NE];
__device__ float g_ew[NE];
__device__ float g_t [NN * HID];
__device__ float g_t2[NN * HID];
__device__ float g_u [NN * HID];
__device__ float g_c [NN * OUTC];
__device__ float g_sum[3 * HID];
__device__ float g_sq [3 * HID];

// ---------------------------------------------------------------------------
// helpers
// ---------------------------------------------------------------------------
__device__ __forceinline__ void bn_params(float sum, float sq, float& m, float& s) {
    const float invN = 1.f / (float)NN;
    m = sum * invN;
    float v = sq * invN - m * m;
    s = rsqrtf(v + 1e-5f);
}

__device__ __forceinline__ uint32_t pk(__nv_bfloat16 x, __nv_bfloat16 y) {
    __nv_bfloat162 h2;
    h2.x = x; h2.y = y;
    return *(uint32_t*)&h2;
}
__device__ __forceinline__ void split2(float x, float y, uint32_t& hi, uint32_t& lo) {
    __nv_bfloat16 hx = __float2bfloat16_rn(x);
    __nv_bfloat16 hy = __float2bfloat16_rn(y);
    float rx = x - __bfloat162float(hx);
    float ry = y - __bfloat162float(hy);
    hi = pk(hx, hy);
    lo = pk(__float2bfloat16_rn(rx), __float2bfloat16_rn(ry));
}

__device__ __forceinline__ void mma_bf16(float& c0, float& c1, float& c2, float& c3,
                                         uint32_t a0, uint32_t a1, uint32_t a2, uint32_t a3,
                                         uint32_t b0, uint32_t b1) {
    asm volatile(
        "mma.sync.aligned.m16n8k16.row.col.f32.bf16.bf16.f32 "
        "{%0,%1,%2,%3}, {%4,%5,%6,%7}, {%8,%9}, {%0,%1,%2,%3};"
        : "+f"(c0), "+f"(c1), "+f"(c2), "+f"(c3)
        : "r"(a0), "r"(a1), "r"(a2), "r"(a3), "r"(b0), "r"(b1));
}

// ---------------------------------------------------------------------------
// Prep kernels
// ---------------------------------------------------------------------------
__global__ void zero_prep_kernel() {
    int i = blockIdx.x * blockDim.x + threadIdx.x;
    if (i < NN) { g_cnt[i] = 0; g_fill[i] = 0; }
    if (i < 3 * HID) { g_sum[i] = 0.f; g_sq[i] = 0.f; }
}

__global__ void cnt_kernel(const int* __restrict__ ei) {
    int e = blockIdx.x * blockDim.x + threadIdx.x;
    if (e >= NE) return;
    int s = ei[e];
    int d = ei[NE + e];
    if (s != d) atomicAdd(&g_cnt[d], 1);
}

__global__ void scan1_kernel() {
    __shared__ int sh[256];
    int i = blockIdx.x * 256 + threadIdx.x;
    sh[threadIdx.x] = (i < NN) ? g_cnt[i] : 0;
    __syncthreads();
    for (int o = 128; o > 0; o >>= 1) {
        if (threadIdx.x < o) sh[threadIdx.x] += sh[threadIdx.x + o];
        __syncthreads();
    }
    if (threadIdx.x == 0) g_bsum[blockIdx.x] = sh[0];
}

__global__ void scan2_kernel() {
    __shared__ int sh[256];
    int t = threadIdx.x;
    int v = (t < SCB) ? g_bsum[t] : 0;
    sh[t] = v;
    __syncthreads();
    for (int o = 1; o < 256; o <<= 1) {
        int add = (t >= o) ? sh[t - o] : 0;
        __syncthreads();
        sh[t] += add;
        __syncthreads();
    }
    if (t < SCB) g_boff[t] = sh[t] - v;
    if (t == 255) g_rowptr[NN] = sh[255];
}

__global__ void scan3_kernel() {
    __shared__ int sh[256];
    int t = threadIdx.x;
    int i = blockIdx.x * 256 + t;
    int v = (i < NN) ? g_cnt[i] : 0;
    sh[t] = v;
    __syncthreads();
    for (int o = 1; o < 256; o <<= 1) {
        int add = (t >= o) ? sh[t - o] : 0;
        __syncthreads();
        sh[t] += add;
        __syncthreads();
    }
    if (i < NN) {
        g_rowptr[i] = g_boff[blockIdx.x] + sh[t] - v;
        float d = (float)v + 1.f;
        g_dinv[i]  = rsqrtf(d);
        g_selfw[i] = 1.f / d;
    }
}

__global__ void fill_kernel(const int* __restrict__ ei) {
    int e = blockIdx.x * blockDim.x + threadIdx.x;
    if (e >= NE) return;
    int s = ei[e];
    int d = ei[NE + e];
    if (s == d) return;
    int pos = g_rowptr[d] + atomicAdd(&g_fill[d], 1);
    g_col[pos] = s;
    g_ew[pos] = g_dinv[s] * g_dinv[d];
}

// ---------------------------------------------------------------------------
// bf16 3-term mma.sync GEMM with warp n-split.
// TILE rows/block; NTH threads; RW = TILE/16 row-warps; SP = warps/RW (1 or 2).
// Warp w: rows [(w%RW)*16, +16), n-tiles [(w/RW)*NT/SP, +NT/SP).
// ---------------------------------------------------------------------------
template <int K, int NOUT, int TILE, int NTH, int NORM, int STATS, int BLEND>
__global__ void __launch_bounds__(NTH)
gemm_mma(const float* __restrict__ A, const float* __restrict__ Wg,
         float* __restrict__ Out, const float* __restrict__ blendSrc,
         const float* __restrict__ sIn, const float* __restrict__ qIn,
         float beta, float* __restrict__ sOut, float* __restrict__ qOut) {
    constexpr int RSA = (K == 128) ? 136 : 104;   // padded row stride in bf16
    constexpr int RS2 = RSA / 2;                  // in u32 (bf16 pairs)
    constexpr int NT = NOUT / 8;                  // n-tiles total
    constexpr int NK = K / 16;                    // k-steps
    constexpr int RW = TILE / 16;                 // row-warps
    constexpr int NW = NTH / 32;                  // warps
    constexpr int SP = NW / RW;                   // n-split factor
    constexpr int NTW = NT / SP;                  // n-tiles per warp

    extern __shared__ char smraw[];
    uint32_t* Ahi = (uint32_t*)smraw;             // TILE*RS2
    uint32_t* Alo = Ahi + TILE * RS2;
    uint32_t* Bhi = Alo + TILE * RS2;             // NOUT*RS2
    uint32_t* Blo = Bhi + NOUT * RS2;
    float* bnM = (float*)(Blo + NOUT * RS2);      // K (NORM)
    float* bnS = bnM + (NORM ? K : 0);
    float* cS  = bnS + (NORM ? K : 0);            // NOUT (STATS)
    float* cQ  = cS + (STATS ? NOUT : 0);

    int tid = threadIdx.x;
    int rowbase = blockIdx.x * TILE;

    if (NORM && tid < K) {
        float m, s;
        bn_params(sIn[tid], qIn[tid], m, s);
        bnM[tid] = m;
        bnS[tid] = s;
    }
    if (STATS && tid < NOUT) { cS[tid] = 0.f; cQ[tid] = 0.f; }
    __syncthreads();   // bn/stats SMEM visible before staging

    // ---- stage A (TILE x K), split hi/lo ----
    for (int i = tid; i < TILE * (K / 4); i += NTH) {
        int r = i / (K / 4), c4 = i % (K / 4);
        int row = rowbase + r;
        float4 v = (row < NN) ? __ldg((const float4*)&A[(size_t)row * K + c4 * 4])
                              : make_float4(0.f, 0.f, 0.f, 0.f);
        if (NORM) {
            int c = c4 * 4;
            v.x = fmaxf((v.x - bnM[c + 0]) * bnS[c + 0], 0.f);
            v.y = fmaxf((v.y - bnM[c + 1]) * bnS[c + 1], 0.f);
            v.z = fmaxf((v.z - bnM[c + 2]) * bnS[c + 2], 0.f);
            v.w = fmaxf((v.w - bnM[c + 3]) * bnS[c + 3], 0.f);
        }
        uint32_t h0, l0, h1, l1;
        split2(v.x, v.y, h0, l0);
        split2(v.z, v.w, h1, l1);
        int idx = r * RS2 + c4 * 2;
        Ahi[idx] = h0; Ahi[idx + 1] = h1;
        Alo[idx] = l0; Alo[idx + 1] = l1;
    }
    // ---- stage B = W (NOUT x K), split hi/lo ----
    for (int i = tid; i < NOUT * (K / 4); i += NTH) {
        int n = i / (K / 4), c4 = i % (K / 4);
        float4 v = __ldg((const float4*)&Wg[(size_t)n * K + c4 * 4]);
        uint32_t h0, l0, h1, l1;
        split2(v.x, v.y, h0, l0);
        split2(v.z, v.w, h1, l1);
        int idx = n * RS2 + c4 * 2;
        Bhi[idx] = h0; Bhi[idx + 1] = h1;
        Blo[idx] = l0; Blo[idx + 1] = l1;
    }
    __syncthreads();

    // ---- mainloop ----
    int w = tid >> 5, lane = tid & 31;
    int g = lane >> 2, t = lane & 3;
    int wrow = (w % RW) * 16;
    int ntbase = (w / RW) * NTW;
    int aoff0 = (wrow + g) * RS2;
    int aoff1 = (wrow + g + 8) * RS2;

    float acc[NTW][4];
#pragma unroll
    for (int nt = 0; nt < NTW; nt++)
#pragma unroll
        for (int j = 0; j < 4; j++) acc[nt][j] = 0.f;

#pragma unroll
    for (int pass = 0; pass < 3; pass++) {
        const uint32_t* Aa = (pass == 2) ? Alo : Ahi;
        const uint32_t* Bb = (pass == 1) ? Blo : Bhi;
#pragma unroll
        for (int ks = 0; ks < NK; ks++) {
            uint32_t a0 = Aa[aoff0 + ks * 8 + t];
            uint32_t a1 = Aa[aoff1 + ks * 8 + t];
            uint32_t a2 = Aa[aoff0 + ks * 8 + 4 + t];
            uint32_t a3 = Aa[aoff1 + ks * 8 + 4 + t];
#pragma unroll
            for (int nt = 0; nt < NTW; nt++) {
                int n8 = (ntbase + nt) * 8 + g;
                uint32_t b0 = Bb[n8 * RS2 + ks * 8 + t];
                uint32_t b1 = Bb[n8 * RS2 + ks * 8 + 4 + t];
                mma_bf16(acc[nt][0], acc[nt][1], acc[nt][2], acc[nt][3],
                         a0, a1, a2, a3, b0, b1);
            }
        }
    }

    // ---- epilogue ----
    int r0 = rowbase + wrow + g;
    int r1 = r0 + 8;
    bool v0 = r0 < NN, v1 = r1 < NN;

#pragma unroll
    for (int nt = 0; nt < NTW; nt++) {
        int c = (ntbase + nt) * 8 + 2 * t;
        float d0 = acc[nt][0], d1 = acc[nt][1];
        float d2 = acc[nt][2], d3 = acc[nt][3];
        if (BLEND) {
            float2 b0 = v0 ? *(const float2*)&blendSrc[(size_t)r0 * NOUT + c]
                           : make_float2(0.f, 0.f);
            float2 b1 = v1 ? *(const float2*)&blendSrc[(size_t)r1 * NOUT + c]
                           : make_float2(0.f, 0.f);
            float m0 = bnM[c], m1 = bnM[c + 1], s0 = bnS[c], s1 = bnS[c + 1];
            d0 = beta * d0 + (1.f - beta) * fmaxf((b0.x - m0) * s0, 0.f);
            d1 = beta * d1 + (1.f - beta) * fmaxf((b0.y - m1) * s1, 0.f);
            d2 = beta * d2 + (1.f - beta) * fmaxf((b1.x - m0) * s0, 0.f);
            d3 = beta * d3 + (1.f - beta) * fmaxf((b1.y - m1) * s1, 0.f);
        }
        if (v0) *(float2*)&Out[(size_t)r0 * NOUT + c] = make_float2(d0, d1);
        if (v1) *(float2*)&Out[(size_t)r1 * NOUT + c] = make_float2(d2, d3);
        if (STATS) {
            float e0 = v0 ? d0 : 0.f, e1 = v0 ? d1 : 0.f;
            float e2 = v1 ? d2 : 0.f, e3 = v1 ? d3 : 0.f;
            float sa = e0 + e2, sb = e1 + e3;
            float qa = e0 * e0 + e2 * e2, qb = e1 * e1 + e3 * e3;
#pragma unroll
            for (int o = 4; o < 32; o <<= 1) {
                sa += __shfl_xor_sync(0xFFFFFFFFu, sa, o);
                sb += __shfl_xor_sync(0xFFFFFFFFu, sb, o);
                qa += __shfl_xor_sync(0xFFFFFFFFu, qa, o);
                qb += __shfl_xor_sync(0xFFFFFFFFu, qb, o);
            }
            if (lane < 4) {
                atomicAdd(&cS[c], sa);
                atomicAdd(&cS[c + 1], sb);
                atomicAdd(&cQ[c], qa);
                atomicAdd(&cQ[c + 1], qb);
            }
        }
    }

    if (STATS) {
        __syncthreads();
        if (tid < NOUT) {
            atomicAdd(&sOut[tid], cS[tid]);
            atomicAdd(&qOut[tid], cQ[tid]);
        }
    }
}

// ---------------------------------------------------------------------------
// CSR gather SpMM, warp per node (F=96).
// ---------------------------------------------------------------------------
template <int F, int MODE>
__global__ void gather_kernel(const float* __restrict__ X, float* __restrict__ Y,
                              const float* __restrict__ h0raw,
                              const float* __restrict__ sums0,
                              const float* __restrict__ sq0,
                              float* __restrict__ sumsOut,
                              float* __restrict__ sqOut) {
    constexpr int NV = F / 4;
    __shared__ __align__(16) float ssum[HID];
    __shared__ __align__(16) float ssq[HID];
    __shared__ __align__(16) float sm_m[HID];
    __shared__ __align__(16) float sm_s[HID];
    int tid = threadIdx.x;
    if (MODE == 1) {
        if (tid < F) {
            ssum[tid] = 0.f;
            ssq[tid] = 0.f;
            float m, s;
            bn_params(sums0[tid], sq0[tid], m, s);
            sm_m[tid] = m;
            sm_s[tid] = s;
        }
        __syncthreads();
    }
    int node = blockIdx.x * (blockDim.x >> 5) + (tid >> 5);
    int lane = tid & 31;
    bool act = lane < NV;
    const float4* Xv = (const float4*)X;

    float4 sum = make_float4(0.f, 0.f, 0.f, 0.f);
    int p   = g_rowptr[node];
    int end = g_rowptr[node + 1];

    for (; p + 4 <= end; p += 4) {
        int   c0 = __ldg(&g_col[p]),     c1 = __ldg(&g_col[p + 1]);
        int   c2 = __ldg(&g_col[p + 2]), c3 = __ldg(&g_col[p + 3]);
        float w0 = __ldg(&g_ew[p]),      w1 = __ldg(&g_ew[p + 1]);
        float w2 = __ldg(&g_ew[p + 2]),  w3 = __ldg(&g_ew[p + 3]);
        if (act) {
            float4 v0 = __ldg(&Xv[(size_t)c0 * NV + lane]);
            float4 v1 = __ldg(&Xv[(size_t)c1 * NV + lane]);
            float4 v2 = __ldg(&Xv[(size_t)c2 * NV + lane]);
            float4 v3 = __ldg(&Xv[(size_t)c3 * NV + lane]);
            sum.x += w0 * v0.x + w1 * v1.x + w2 * v2.x + w3 * v3.x;
            sum.y += w0 * v0.y + w1 * v1.y + w2 * v2.y + w3 * v3.y;
            sum.z += w0 * v0.z + w1 * v1.z + w2 * v2.z + w3 * v3.z;
            sum.w += w0 * v0.w + w1 * v1.w + w2 * v2.w + w3 * v3.w;
        }
    }
    for (; p < end; p++) {
        int c = __ldg(&g_col[p]);
        float w = __ldg(&g_ew[p]);
        if (act) {
            float4 v = __ldg(&Xv[(size_t)c * NV + lane]);
            sum.x += w * v.x; sum.y += w * v.y;
            sum.z += w * v.z; sum.w += w * v.w;
        }
    }

    if (act) {
        float sw = g_selfw[node];
        float4 xv = __ldg(&Xv[(size_t)node * NV + lane]);
        float4 v;
        v.x = sum.x + sw * xv.x;
        v.y = sum.y + sw * xv.y;
        v.z = sum.z + sw * xv.z;
        v.w = sum.w + sw * xv.w;
        if (MODE == 1) {
            float4 m  = ((const float4*)sm_m)[lane];
            float4 s  = ((const float4*)sm_s)[lane];
            float4 hr = __ldg(&((const float4*)h0raw)[(size_t)node * NV + lane]);
            v.x = 0.9f * v.x + 0.1f * fmaxf((hr.x - m.x) * s.x, 0.f);
            v.y = 0.9f * v.y + 0.1f * fmaxf((hr.y - m.y) * s.y, 0.f);
            v.z = 0.9f * v.z + 0.1f * fmaxf((hr.z - m.z) * s.z, 0.f);
            v.w = 0.9f * v.w + 0.1f * fmaxf((hr.w - m.w) * s.w, 0.f);
        }
        ((float4*)Y)[(size_t)node * NV + lane] = v;
        if (MODE == 1) {
            int col = lane * 4;
            atomicAdd(&ssum[col + 0], v.x);
            atomicAdd(&ssum[col + 1], v.y);
            atomicAdd(&ssum[col + 2], v.z);
            atomicAdd(&ssum[col + 3], v.w);
            atomicAdd(&ssq[col + 0], v.x * v.x);
            atomicAdd(&ssq[col + 1], v.y * v.y);
            atomicAdd(&ssq[col + 2], v.z * v.z);
            atomicAdd(&ssq[col + 3], v.w * v.w);
        }
    }

    if (MODE == 1) {
        __syncthreads();
        if (tid < F) {
            atomicAdd(&sumsOut[tid], ssum[tid]);
            atomicAdd(&sqOut[tid], ssq[tid]);
        }
    }
}

// ---------------------------------------------------------------------------
// Final gather (F=40): two nodes per warp (half-warp each, 10 active lanes).
// ---------------------------------------------------------------------------
__global__ void gather40_kernel(const float* __restrict__ X, float* __restrict__ Y) {
    constexpr int NV = OUTC / 4;
    int lane = threadIdx.x & 31;
    int half = lane >> 4;
    int sub  = lane & 15;
    int node = (blockIdx.x * (blockDim.x >> 5) + (threadIdx.x >> 5)) * 2 + half;
    if (node >= NN) return;
    bool act = sub < NV;
    const float4* Xv = (const float4*)X;

    float4 sum = make_float4(0.f, 0.f, 0.f, 0.f);
    int p   = g_rowptr[node];
    int end = g_rowptr[node + 1];

    for (; p + 4 <= end; p += 4) {
        int   c0 = __ldg(&g_col[p]),     c1 = __ldg(&g_col[p + 1]);
        int   c2 = __ldg(&g_col[p + 2]), c3 = __ldg(&g_col[p + 3]);
        float w0 = __ldg(&g_ew[p]),      w1 = __ldg(&g_ew[p + 1]);
        float w2 = __ldg(&g_ew[p + 2]),  w3 = __ldg(&g_ew[p + 3]);
        if (act) {
            float4 v0 = __ldg(&Xv[(size_t)c0 * NV + sub]);
            float4 v1 = __ldg(&Xv[(size_t)c1 * NV + sub]);
            float4 v2 = __ldg(&Xv[(size_t)c2 * NV + sub]);
            float4 v3 = __ldg(&Xv[(size_t)c3 * NV + sub]);
            sum.x += w0 * v0.x + w1 * v1.x + w2 * v2.x + w3 * v3.x;
            sum.y += w0 * v0.y + w1 * v1.y + w2 * v2.y + w3 * v3.y;
            sum.z += w0 * v0.z + w1 * v1.z + w2 * v2.z + w3 * v3.z;
            sum.w += w0 * v0.w + w1 * v1.w + w2 * v2.w + w3 * v3.w;
        }
    }
    for (; p < end; p++) {
        int c = __ldg(&g_col[p]);
        float w = __ldg(&g_ew[p]);
        if (act) {
            float4 v = __ldg(&Xv[(size_t)c * NV + sub]);
            sum.x += w * v.x; sum.y += w * v.y;
            sum.z += w * v.z; sum.w += w * v.w;
        }
    }

    if (act) {
        float sw = g_selfw[node];
        float4 xv = __ldg(&Xv[(size_t)node * NV + sub]);
        float4 v;
        v.x = sum.x + sw * xv.x;
        v.y = sum.y + sw * xv.y;
        v.z = sum.z + sw * xv.z;
        v.w = sum.w + sw * xv.w;
        ((float4*)Y)[(size_t)node * NV + sub] = v;
    }
}

// ---------------------------------------------------------------------------
extern "C" void kernel_launch(void* const* d_in, const int* in_sizes, int n_in,
                              void* d_out, int out_size) {
    const float* x  = (const float*)d_in[0];
    const int*   ei = (const int*)d_in[1];
    const float* W0 = (const float*)d_in[2];
    const float* W1 = (const float*)d_in[3];
    const float* W2 = (const float*)d_in[4];
    const float* W3 = (const float*)d_in[5];
    float* out = (float*)d_out;

    float *pt, *pt2, *pu, *pc, *psum, *psq;
    cudaGetSymbolAddress((void**)&pt, g_t);
    cudaGetSymbolAddress((void**)&pt2, g_t2);
    cudaGetSymbolAddress((void**)&pu, g_u);
    cudaGetSymbolAddress((void**)&pc, g_c);
    cudaGetSymbolAddress((void**)&psum, g_sum);
    cudaGetSymbolAddress((void**)&psq, g_sq);

    const int gbE = (NE + 255) / 256;
    const int gbN = (NN + 255) / 256;
    const int gbG0 = (NN + 255) / 256;   // 196 tiles of 256 rows (k0)
    const int gbG1 = (NN + 127) / 128;   // 391 tiles of 128 rows (k12, k3)
    const int gbW = NN / 16;
    const int gbW40 = (NN + 31) / 32;

    float* s0m = psum + 0 * HID; float* s0q = psq + 0 * HID;
    float* s1m = psum + 1 * HID; float* s1q = psq + 1 * HID;
    float* s2m = psum + 2 * HID; float* s2q = psq + 2 * HID;

    // dynamic smem
    const int sm0 = 256 * 68 * 8 + 96 * 68 * 8 + 96 * 8;           // 192,256
    const int sm1 = 128 * 52 * 8 + 96 * 52 * 8 + 96 * 8 + 96 * 8;  // 94,720
    const int sm3 = 128 * 52 * 8 + 40 * 52 * 8 + 96 * 8;           // 70,656

    auto k0  = gemm_mma<INC, HID, 256, 1024, 0, 1, 0>;  // 32 warps, n-split 2
    auto k12 = gemm_mma<HID, HID, 128, 512, 1, 0, 1>;   // 16 warps, n-split 2
    auto k3  = gemm_mma<HID, OUTC, 128, 256, 1, 0, 0>;  // 8 warps, no split
    cudaFuncSetAttribute(k0, cudaFuncAttributeMaxDynamicSharedMemorySize, sm0);
    cudaFuncSetAttribute(k12, cudaFuncAttributeMaxDynamicSharedMemorySize, sm1);
    cudaFuncSetAttribute(k3, cudaFuncAttributeMaxDynamicSharedMemorySize, sm3);

    // Side stream + events for capture-safe fork/join (leaked by design).
    cudaStream_t s2;
    cudaStreamCreateWithFlags(&s2, cudaStreamNonBlocking);
    cudaEvent_t eFork, eJoin;
    cudaEventCreateWithFlags(&eFork, cudaEventDisableTiming);
    cudaEventCreateWithFlags(&eJoin, cudaEventDisableTiming);

    // ---- zero (both branches depend on it) ----
    zero_prep_kernel<<<gbN, 256>>>();
    cudaEventRecord(eFork, 0);
    cudaStreamWaitEvent(s2, eFork, 0);

    // Submission order keeps k0 at index 3 (ncu capture slot).
    cnt_kernel<<<gbE, 256, 0, s2>>>(ei);
    scan1_kernel<<<SCB, 256, 0, s2>>>();
    k0<<<gbG0, 1024, sm0>>>(x, W0, pt, nullptr, nullptr, nullptr, 1.f, s0m, s0q);
    scan2_kernel<<<1, 256, 0, s2>>>();
    scan3_kernel<<<SCB, 256, 0, s2>>>();
    fill_kernel<<<gbE, 256, 0, s2>>>(ei);
    cudaEventRecord(eJoin, s2);

    // ---- layer 1 GEMM (stream 0, no CSR dependence) ----
    k12<<<gbG1, 512, sm1>>>(pt, W1, pt2, pt, s0m, s0q, 0.5f, nullptr, nullptr);

    // ---- join: gather1 needs CSR + selfw ----
    cudaStreamWaitEvent(0, eJoin, 0);
    gather_kernel<HID, 1><<<gbW, 512>>>(pt2, pu, pt, s0m, s0q, s1m, s1q);

    // ---- layer 2 (beta = 0.25) ----
    k12<<<gbG1, 512, sm1>>>(pu, W2, pt2, pu, s1m, s1q, 0.25f, nullptr, nullptr);
    gather_kernel<HID, 1><<<gbW, 512>>>(pt2, pu, pt, s0m, s0q, s2m, s2q);

    // ---- final: c = bn2relu(u) @ W3^T ; out = spmm(c) ----
    k3<<<gbG1, 256, sm3>>>(pu, W3, pc, nullptr, s2m, s2q, 1.f, nullptr, nullptr);
    gather40_kernel<<<gbW40, 512>>>(pc, out);
}

// round 17
// speedup vs baseline: 2.0863x; 1.0296x over previous
#include <cuda_runtime.h>
#include <cuda_bf16.h>
#include <cstdint>

#define NN 50000
#define NE 800000
#define INC 128
#define HID 96
#define OUTC 40
#define SCB 196   // scan blocks: 196*256 = 50176 >= NN

__device__ float g_dinv[NN];
__device__ float g_selfw[NN];
__device__ int   g_cnt[NN];
__device__ int   g_fill[NN];
__device__ int   g_rowptr[NN + 1];
__device__ int   g_bsum[256];
__device__ int   g_boff[256];
__device__ int   g_col[NE];
__device__ float g_ew[NE];
__device__ float g_t [NN * HID];
__device__ float g_t2[NN * HID];
__device__ float g_u [NN * HID];
__device__ float g_c [NN * OUTC];
__device__ float g_sum[3 * HID];
__device__ float g_sq [3 * HID];

// ---------------------------------------------------------------------------
// helpers
// ---------------------------------------------------------------------------
__device__ __forceinline__ void bn_params(float sum, float sq, float& m, float& s) {
    const float invN = 1.f / (float)NN;
    m = sum * invN;
    float v = sq * invN - m * m;
    s = rsqrtf(v + 1e-5f);
}

__device__ __forceinline__ uint32_t pk(__nv_bfloat16 x, __nv_bfloat16 y) {
    __nv_bfloat162 h2;
    h2.x = x; h2.y = y;
    return *(uint32_t*)&h2;
}
__device__ __forceinline__ void split2(float x, float y, uint32_t& hi, uint32_t& lo) {
    __nv_bfloat16 hx = __float2bfloat16_rn(x);
    __nv_bfloat16 hy = __float2bfloat16_rn(y);
    float rx = x - __bfloat162float(hx);
    float ry = y - __bfloat162float(hy);
    hi = pk(hx, hy);
    lo = pk(__float2bfloat16_rn(rx), __float2bfloat16_rn(ry));
}
// reconstruct fp32 pair from hi/lo bf16 pairs
__device__ __forceinline__ float2 rec2(uint32_t h, uint32_t l) {
    __nv_bfloat162 hh = *(__nv_bfloat162*)&h;
    __nv_bfloat162 ll = *(__nv_bfloat162*)&l;
    return make_float2(__bfloat162float(hh.x) + __bfloat162float(ll.x),
                       __bfloat162float(hh.y) + __bfloat162float(ll.y));
}

__device__ __forceinline__ void mma_bf16(float& c0, float& c1, float& c2, float& c3,
                                         uint32_t a0, uint32_t a1, uint32_t a2, uint32_t a3,
                                         uint32_t b0, uint32_t b1) {
    asm volatile(
        "mma.sync.aligned.m16n8k16.row.col.f32.bf16.bf16.f32 "
        "{%0,%1,%2,%3}, {%4,%5,%6,%7}, {%8,%9}, {%0,%1,%2,%3};"
        : "+f"(c0), "+f"(c1), "+f"(c2), "+f"(c3)
        : "r"(a0), "r"(a1), "r"(a2), "r"(a3), "r"(b0), "r"(b1));
}

// ---------------------------------------------------------------------------
// Prep kernels
// ---------------------------------------------------------------------------
__global__ void zero_prep_kernel() {
    int i = blockIdx.x * blockDim.x + threadIdx.x;
    if (i < NN) { g_cnt[i] = 0; g_fill[i] = 0; }
    if (i < 3 * HID) { g_sum[i] = 0.f; g_sq[i] = 0.f; }
}

__global__ void cnt_kernel(const int* __restrict__ ei) {
    int e = blockIdx.x * blockDim.x + threadIdx.x;
    if (e >= NE) return;
    int s = ei[e];
    int d = ei[NE + e];
    if (s != d) atomicAdd(&g_cnt[d], 1);
}

__global__ void scan1_kernel() {
    __shared__ int sh[256];
    int i = blockIdx.x * 256 + threadIdx.x;
    sh[threadIdx.x] = (i < NN) ? g_cnt[i] : 0;
    __syncthreads();
    for (int o = 128; o > 0; o >>= 1) {
        if (threadIdx.x < o) sh[threadIdx.x] += sh[threadIdx.x + o];
        __syncthreads();
    }
    if (threadIdx.x == 0) g_bsum[blockIdx.x] = sh[0];
}

__global__ void scan2_kernel() {
    __shared__ int sh[256];
    int t = threadIdx.x;
    int v = (t < SCB) ? g_bsum[t] : 0;
    sh[t] = v;
    __syncthreads();
    for (int o = 1; o < 256; o <<= 1) {
        int add = (t >= o) ? sh[t - o] : 0;
        __syncthreads();
        sh[t] += add;
        __syncthreads();
    }
    if (t < SCB) g_boff[t] = sh[t] - v;
    if (t == 255) g_rowptr[NN] = sh[255];
}

__global__ void scan3_kernel() {
    __shared__ int sh[256];
    int t = threadIdx.x;
    int i = blockIdx.x * 256 + t;
    int v = (i < NN) ? g_cnt[i] : 0;
    sh[t] = v;
    __syncthreads();
    for (int o = 1; o < 256; o <<= 1) {
        int add = (t >= o) ? sh[t - o] : 0;
        __syncthreads();
        sh[t] += add;
        __syncthreads();
    }
    if (i < NN) {
        g_rowptr[i] = g_boff[blockIdx.x] + sh[t] - v;
        float d = (float)v + 1.f;
        g_dinv[i]  = rsqrtf(d);
        g_selfw[i] = 1.f / d;
    }
}

__global__ void fill_kernel(const int* __restrict__ ei) {
    int e = blockIdx.x * blockDim.x + threadIdx.x;
    if (e >= NE) return;
    int s = ei[e];
    int d = ei[NE + e];
    if (s == d) return;
    int pos = g_rowptr[d] + atomicAdd(&g_fill[d], 1);
    g_col[pos] = s;
    g_ew[pos] = g_dinv[s] * g_dinv[d];
}

// ---------------------------------------------------------------------------
// bf16 3-term mma.sync GEMM with warp n-split.
// TILE rows/block; NTH threads; RW = TILE/16 row-warps; SP = warps/RW.
// BLEND: 0 = none, 2 = blend with staged SMEM A tile (requires NOUT == K,
//        blend operand reconstructed as hi+lo — the exact staged value).
// ---------------------------------------------------------------------------
template <int K, int NOUT, int TILE, int NTH, int NORM, int STATS, int BLEND>
__global__ void __launch_bounds__(NTH)
gemm_mma(const float* __restrict__ A, const float* __restrict__ Wg,
         float* __restrict__ Out,
         const float* __restrict__ sIn, const float* __restrict__ qIn,
         float beta, float* __restrict__ sOut, float* __restrict__ qOut) {
    constexpr int RSA = (K == 128) ? 136 : 104;   // padded row stride in bf16
    constexpr int RS2 = RSA / 2;                  // in u32 (bf16 pairs)
    constexpr int NT = NOUT / 8;                  // n-tiles total
    constexpr int NK = K / 16;                    // k-steps
    constexpr int RW = TILE / 16;                 // row-warps
    constexpr int NW = NTH / 32;                  // warps
    constexpr int SP = NW / RW;                   // n-split factor
    constexpr int NTW = NT / SP;                  // n-tiles per warp

    extern __shared__ char smraw[];
    uint32_t* Ahi = (uint32_t*)smraw;             // TILE*RS2
    uint32_t* Alo = Ahi + TILE * RS2;
    uint32_t* Bhi = Alo + TILE * RS2;             // NOUT*RS2
    uint32_t* Blo = Bhi + NOUT * RS2;
    float* bnM = (float*)(Blo + NOUT * RS2);      // K (NORM)
    float* bnS = bnM + (NORM ? K : 0);
    float* cS  = bnS + (NORM ? K : 0);            // NOUT (STATS)
    float* cQ  = cS + (STATS ? NOUT : 0);

    int tid = threadIdx.x;
    int rowbase = blockIdx.x * TILE;

    if (NORM && tid < K) {
        float m, s;
        bn_params(sIn[tid], qIn[tid], m, s);
        bnM[tid] = m;
        bnS[tid] = s;
    }
    if (STATS && tid < NOUT) { cS[tid] = 0.f; cQ[tid] = 0.f; }
    __syncthreads();   // bn/stats SMEM visible before staging

    // ---- stage A (TILE x K), split hi/lo ----
    for (int i = tid; i < TILE * (K / 4); i += NTH) {
        int r = i / (K / 4), c4 = i % (K / 4);
        int row = rowbase + r;
        float4 v = (row < NN) ? __ldg((const float4*)&A[(size_t)row * K + c4 * 4])
                              : make_float4(0.f, 0.f, 0.f, 0.f);
        if (NORM) {
            int c = c4 * 4;
            v.x = fmaxf((v.x - bnM[c + 0]) * bnS[c + 0], 0.f);
            v.y = fmaxf((v.y - bnM[c + 1]) * bnS[c + 1], 0.f);
            v.z = fmaxf((v.z - bnM[c + 2]) * bnS[c + 2], 0.f);
            v.w = fmaxf((v.w - bnM[c + 3]) * bnS[c + 3], 0.f);
        }
        uint32_t h0, l0, h1, l1;
        split2(v.x, v.y, h0, l0);
        split2(v.z, v.w, h1, l1);
        int idx = r * RS2 + c4 * 2;
        Ahi[idx] = h0; Ahi[idx + 1] = h1;
        Alo[idx] = l0; Alo[idx + 1] = l1;
    }
    // ---- stage B = W (NOUT x K), split hi/lo ----
    for (int i = tid; i < NOUT * (K / 4); i += NTH) {
        int n = i / (K / 4), c4 = i % (K / 4);
        float4 v = __ldg((const float4*)&Wg[(size_t)n * K + c4 * 4]);
        uint32_t h0, l0, h1, l1;
        split2(v.x, v.y, h0, l0);
        split2(v.z, v.w, h1, l1);
        int idx = n * RS2 + c4 * 2;
        Bhi[idx] = h0; Bhi[idx + 1] = h1;
        Blo[idx] = l0; Blo[idx + 1] = l1;
    }
    __syncthreads();

    // ---- mainloop ----
    int w = tid >> 5, lane = tid & 31;
    int g = lane >> 2, t = lane & 3;
    int wrow = (w % RW) * 16;
    int ntbase = (w / RW) * NTW;
    int aoff0 = (wrow + g) * RS2;
    int aoff1 = (wrow + g + 8) * RS2;

    float acc[NTW][4];
#pragma unroll
    for (int nt = 0; nt < NTW; nt++)
#pragma unroll
        for (int j = 0; j < 4; j++) acc[nt][j] = 0.f;

#pragma unroll
    for (int pass = 0; pass < 3; pass++) {
        const uint32_t* Aa = (pass == 2) ? Alo : Ahi;
        const uint32_t* Bb = (pass == 1) ? Blo : Bhi;
#pragma unroll
        for (int ks = 0; ks < NK; ks++) {
            uint32_t a0 = Aa[aoff0 + ks * 8 + t];
            uint32_t a1 = Aa[aoff1 + ks * 8 + t];
            uint32_t a2 = Aa[aoff0 + ks * 8 + 4 + t];
            uint32_t a3 = Aa[aoff1 + ks * 8 + 4 + t];
#pragma unroll
            for (int nt = 0; nt < NTW; nt++) {
                int n8 = (ntbase + nt) * 8 + g;
                uint32_t b0 = Bb[n8 * RS2 + ks * 8 + t];
                uint32_t b1 = Bb[n8 * RS2 + ks * 8 + 4 + t];
                mma_bf16(acc[nt][0], acc[nt][1], acc[nt][2], acc[nt][3],
                         a0, a1, a2, a3, b0, b1);
            }
        }
    }

    // ---- epilogue ----
    int lr0 = wrow + g;
    int lr1 = lr0 + 8;
    int r0 = rowbase + lr0;
    int r1 = r0 + 8;
    bool v0 = r0 < NN, v1 = r1 < NN;

#pragma unroll
    for (int nt = 0; nt < NTW; nt++) {
        int c = (ntbase + nt) * 8 + 2 * t;
        float d0 = acc[nt][0], d1 = acc[nt][1];
        float d2 = acc[nt][2], d3 = acc[nt][3];
        if (BLEND == 2) {
            // blend operand = staged normA(A) tile, reconstructed hi+lo
            int i0 = lr0 * RS2 + (c >> 1);
            int i1 = lr1 * RS2 + (c >> 1);
            float2 b0 = rec2(Ahi[i0], Alo[i0]);
            float2 b1 = rec2(Ahi[i1], Alo[i1]);
            d0 = beta * d0 + (1.f - beta) * b0.x;
            d1 = beta * d1 + (1.f - beta) * b0.y;
            d2 = beta * d2 + (1.f - beta) * b1.x;
            d3 = beta * d3 + (1.f - beta) * b1.y;
        }
        if (v0) *(float2*)&Out[(size_t)r0 * NOUT + c] = make_float2(d0, d1);
        if (v1) *(float2*)&Out[(size_t)r1 * NOUT + c] = make_float2(d2, d3);
        if (STATS) {
            float e0 = v0 ? d0 : 0.f, e1 = v0 ? d1 : 0.f;
            float e2 = v1 ? d2 : 0.f, e3 = v1 ? d3 : 0.f;
            float sa = e0 + e2, sb = e1 + e3;
            float qa = e0 * e0 + e2 * e2, qb = e1 * e1 + e3 * e3;
#pragma unroll
            for (int o = 4; o < 32; o <<= 1) {
                sa += __shfl_xor_sync(0xFFFFFFFFu, sa, o);
                sb += __shfl_xor_sync(0xFFFFFFFFu, sb, o);
                qa += __shfl_xor_sync(0xFFFFFFFFu, qa, o);
                qb += __shfl_xor_sync(0xFFFFFFFFu, qb, o);
            }
            if (lane < 4) {
                atomicAdd(&cS[c], sa);
                atomicAdd(&cS[c + 1], sb);
                atomicAdd(&cQ[c], qa);
                atomicAdd(&cQ[c + 1], qb);
            }
        }
    }

    if (STATS) {
        __syncthreads();
        if (tid < NOUT) {
            atomicAdd(&sOut[tid], cS[tid]);
            atomicAdd(&qOut[tid], cQ[tid]);
        }
    }
}

// ---------------------------------------------------------------------------
// CSR gather SpMM, warp per node (F=96).
// ---------------------------------------------------------------------------
template <int F, int MODE>
__global__ void gather_kernel(const float* __restrict__ X, float* __restrict__ Y,
                              const float* __restrict__ h0raw,
                              const float* __restrict__ sums0,
                              const float* __restrict__ sq0,
                              float* __restrict__ sumsOut,
                              float* __restrict__ sqOut) {
    constexpr int NV = F / 4;
    __shared__ __align__(16) float ssum[HID];
    __shared__ __align__(16) float ssq[HID];
    __shared__ __align__(16) float sm_m[HID];
    __shared__ __align__(16) float sm_s[HID];
    int tid = threadIdx.x;
    if (MODE == 1) {
        if (tid < F) {
            ssum[tid] = 0.f;
            ssq[tid] = 0.f;
            float m, s;
            bn_params(sums0[tid], sq0[tid], m, s);
            sm_m[tid] = m;
            sm_s[tid] = s;
        }
        __syncthreads();
    }
    int node = blockIdx.x * (blockDim.x >> 5) + (tid >> 5);
    int lane = tid & 31;
    bool act = lane < NV;
    const float4* Xv = (const float4*)X;

    float4 sum = make_float4(0.f, 0.f, 0.f, 0.f);
    int p   = g_rowptr[node];
    int end = g_rowptr[node + 1];

    for (; p + 4 <= end; p += 4) {
        int   c0 = __ldg(&g_col[p]),     c1 = __ldg(&g_col[p + 1]);
        int   c2 = __ldg(&g_col[p + 2]), c3 = __ldg(&g_col[p + 3]);
        float w0 = __ldg(&g_ew[p]),      w1 = __ldg(&g_ew[p + 1]);
        float w2 = __ldg(&g_ew[p + 2]),  w3 = __ldg(&g_ew[p + 3]);
        if (act) {
            float4 v0 = __ldg(&Xv[(size_t)c0 * NV + lane]);
            float4 v1 = __ldg(&Xv[(size_t)c1 * NV + lane]);
            float4 v2 = __ldg(&Xv[(size_t)c2 * NV + lane]);
            float4 v3 = __ldg(&Xv[(size_t)c3 * NV + lane]);
            sum.x += w0 * v0.x + w1 * v1.x + w2 * v2.x + w3 * v3.x;
            sum.y += w0 * v0.y + w1 * v1.y + w2 * v2.y + w3 * v3.y;
            sum.z += w0 * v0.z + w1 * v1.z + w2 * v2.z + w3 * v3.z;
            sum.w += w0 * v0.w + w1 * v1.w + w2 * v2.w + w3 * v3.w;
        }
    }
    for (; p < end; p++) {
        int c = __ldg(&g_col[p]);
        float w = __ldg(&g_ew[p]);
        if (act) {
            float4 v = __ldg(&Xv[(size_t)c * NV + lane]);
            sum.x += w * v.x; sum.y += w * v.y;
            sum.z += w * v.z; sum.w += w * v.w;
        }
    }

    if (act) {
        float sw = g_selfw[node];
        float4 xv = __ldg(&Xv[(size_t)node * NV + lane]);
        float4 v;
        v.x = sum.x + sw * xv.x;
        v.y = sum.y + sw * xv.y;
        v.z = sum.z + sw * xv.z;
        v.w = sum.w + sw * xv.w;
        if (MODE == 1) {
            float4 m  = ((const float4*)sm_m)[lane];
            float4 s  = ((const float4*)sm_s)[lane];
            float4 hr = __ldg(&((const float4*)h0raw)[(size_t)node * NV + lane]);
            v.x = 0.9f * v.x + 0.1f * fmaxf((hr.x - m.x) * s.x, 0.f);
            v.y = 0.9f * v.y + 0.1f * fmaxf((hr.y - m.y) * s.y, 0.f);
            v.z = 0.9f * v.z + 0.1f * fmaxf((hr.z - m.z) * s.z, 0.f);
            v.w = 0.9f * v.w + 0.1f * fmaxf((hr.w - m.w) * s.w, 0.f);
        }
        ((float4*)Y)[(size_t)node * NV + lane] = v;
        if (MODE == 1) {
            int col = lane * 4;
            atomicAdd(&ssum[col + 0], v.x);
            atomicAdd(&ssum[col + 1], v.y);
            atomicAdd(&ssum[col + 2], v.z);
            atomicAdd(&ssum[col + 3], v.w);
            atomicAdd(&ssq[col + 0], v.x * v.x);
            atomicAdd(&ssq[col + 1], v.y * v.y);
            atomicAdd(&ssq[col + 2], v.z * v.z);
            atomicAdd(&ssq[col + 3], v.w * v.w);
        }
    }

    if (MODE == 1) {
        __syncthreads();
        if (tid < F) {
            atomicAdd(&sumsOut[tid], ssum[tid]);
            atomicAdd(&sqOut[tid], ssq[tid]);
        }
    }
}

// ---------------------------------------------------------------------------
// Final gather (F=40): two nodes per warp.
// ---------------------------------------------------------------------------
__global__ void gather40_kernel(const float* __restrict__ X, float* __restrict__ Y) {
    constexpr int NV = OUTC / 4;
    int lane = threadIdx.x & 31;
    int half = lane >> 4;
    int sub  = lane & 15;
    int node = (blockIdx.x * (blockDim.x >> 5) + (threadIdx.x >> 5)) * 2 + half;
    if (node >= NN) return;
    bool act = sub < NV;
    const float4* Xv = (const float4*)X;

    float4 sum = make_float4(0.f, 0.f, 0.f, 0.f);
    int p   = g_rowptr[node];
    int end = g_rowptr[node + 1];

    for (; p + 4 <= end; p += 4) {
        int   c0 = __ldg(&g_col[p]),     c1 = __ldg(&g_col[p + 1]);
        int   c2 = __ldg(&g_col[p + 2]), c3 = __ldg(&g_col[p + 3]);
        float w0 = __ldg(&g_ew[p]),      w1 = __ldg(&g_ew[p + 1]);
        float w2 = __ldg(&g_ew[p + 2]),  w3 = __ldg(&g_ew[p + 3]);
        if (act) {
            float4 v0 = __ldg(&Xv[(size_t)c0 * NV + sub]);
            float4 v1 = __ldg(&Xv[(size_t)c1 * NV + sub]);
            float4 v2 = __ldg(&Xv[(size_t)c2 * NV + sub]);
            float4 v3 = __ldg(&Xv[(size_t)c3 * NV + sub]);
            sum.x += w0 * v0.x + w1 * v1.x + w2 * v2.x + w3 * v3.x;
            sum.y += w0 * v0.y + w1 * v1.y + w2 * v2.y + w3 * v3.y;
            sum.z += w0 * v0.z + w1 * v1.z + w2 * v2.z + w3 * v3.z;
            sum.w += w0 * v0.w + w1 * v1.w + w2 * v2.w + w3 * v3.w;
        }
    }
    for (; p < end; p++) {
        int c = __ldg(&g_col[p]);
        float w = __ldg(&g_ew[p]);
        if (act) {
            float4 v = __ldg(&Xv[(size_t)c * NV + sub]);
            sum.x += w * v.x; sum.y += w * v.y;
            sum.z += w * v.z; sum.w += w * v.w;
        }
    }

    if (act) {
        float sw = g_selfw[node];
        float4 xv = __ldg(&Xv[(size_t)node * NV + sub]);
        float4 v;
        v.x = sum.x + sw * xv.x;
        v.y = sum.y + sw * xv.y;
        v.z = sum.z + sw * xv.z;
        v.w = sum.w + sw * xv.w;
        ((float4*)Y)[(size_t)node * NV + sub] = v;
    }
}

// ---------------------------------------------------------------------------
extern "C" void kernel_launch(void* const* d_in, const int* in_sizes, int n_in,
                              void* d_out, int out_size) {
    const float* x  = (const float*)d_in[0];
    const int*   ei = (const int*)d_in[1];
    const float* W0 = (const float*)d_in[2];
    const float* W1 = (const float*)d_in[3];
    const float* W2 = (const float*)d_in[4];
    const float* W3 = (const float*)d_in[5];
    float* out = (float*)d_out;

    float *pt, *pt2, *pu, *pc, *psum, *psq;
    cudaGetSymbolAddress((void**)&pt, g_t);
    cudaGetSymbolAddress((void**)&pt2, g_t2);
    cudaGetSymbolAddress((void**)&pu, g_u);
    cudaGetSymbolAddress((void**)&pc, g_c);
    cudaGetSymbolAddress((void**)&psum, g_sum);
    cudaGetSymbolAddress((void**)&psq, g_sq);

    const int gbE = (NE + 255) / 256;
    const int gbN = (NN + 255) / 256;
    const int gbG0 = (NN + 255) / 256;   // 196 tiles of 256 rows (k0)
    const int gbG1 = (NN + 127) / 128;   // 391 tiles of 128 rows (k12, k3)
    const int gbW = NN / 16;
    const int gbW40 = (NN + 31) / 32;

    float* s0m = psum + 0 * HID; float* s0q = psq + 0 * HID;
    float* s1m = psum + 1 * HID; float* s1q = psq + 1 * HID;
    float* s2m = psum + 2 * HID; float* s2q = psq + 2 * HID;

    // dynamic smem
    const int sm0 = 256 * 68 * 8 + 96 * 68 * 8 + 96 * 8;           // 192,256
    const int sm1 = 128 * 52 * 8 + 96 * 52 * 8 + 96 * 8 + 96 * 8;  // 94,720
    const int sm3 = 128 * 52 * 8 + 40 * 52 * 8 + 96 * 8;           // 70,656

    auto k0  = gemm_mma<INC, HID, 256, 1024, 0, 1, 0>;
    auto k12 = gemm_mma<HID, HID, 128, 512, 1, 0, 2>;   // blend from SMEM tile
    auto k3  = gemm_mma<HID, OUTC, 128, 256, 1, 0, 0>;
    cudaFuncSetAttribute(k0, cudaFuncAttributeMaxDynamicSharedMemorySize, sm0);
    cudaFuncSetAttribute(k12, cudaFuncAttributeMaxDynamicSharedMemorySize, sm1);
    cudaFuncSetAttribute(k3, cudaFuncAttributeMaxDynamicSharedMemorySize, sm3);

    // Side stream + events for capture-safe fork/join (leaked by design).
    cudaStream_t s2;
    cudaStreamCreateWithFlags(&s2, cudaStreamNonBlocking);
    cudaEvent_t eFork, eJoin;
    cudaEventCreateWithFlags(&eFork, cudaEventDisableTiming);
    cudaEventCreateWithFlags(&eJoin, cudaEventDisableTiming);

    // ---- zero (both branches depend on it) ----
    zero_prep_kernel<<<gbN, 256>>>();
    cudaEventRecord(eFork, 0);
    cudaStreamWaitEvent(s2, eFork, 0);

    // Submission order keeps k0 at index 3 (ncu capture slot).
    cnt_kernel<<<gbE, 256, 0, s2>>>(ei);
    scan1_kernel<<<SCB, 256, 0, s2>>>();
    k0<<<gbG0, 1024, sm0>>>(x, W0, pt, nullptr, nullptr, 1.f, s0m, s0q);
    scan2_kernel<<<1, 256, 0, s2>>>();
    scan3_kernel<<<SCB, 256, 0, s2>>>();
    fill_kernel<<<gbE, 256, 0, s2>>>(ei);
    cudaEventRecord(eJoin, s2);

    // ---- layer 1 GEMM (stream 0, no CSR dependence) ----
    k12<<<gbG1, 512, sm1>>>(pt, W1, pt2, s0m, s0q, 0.5f, nullptr, nullptr);

    // ---- join: gather1 needs CSR + selfw ----
    cudaStreamWaitEvent(0, eJoin, 0);
    gather_kernel<HID, 1><<<gbW, 512>>>(pt2, pu, pt, s0m, s0q, s1m, s1q);

    // ---- layer 2 (beta = 0.25) ----
    k12<<<gbG1, 512, sm1>>>(pu, W2, pt2, s1m, s1q, 0.25f, nullptr, nullptr);
    gather_kernel<HID, 1><<<gbW, 512>>>(pt2, pu, pt, s0m, s0q, s2m, s2q);

    // ---- final: c = bn2relu(u) @ W3^T ; out = spmm(c) ----
    k3<<<gbG1, 256, sm3>>>(pu, W3, pc, s2m, s2q, 1.f, nullptr, nullptr);
    gather40_kernel<<<gbW40, 512>>>(pc, out);
}